// round 1
// baseline (speedup 1.0000x reference)
#include <cuda_runtime.h>
#include <cuda_bf16.h>
#include <cstdint>
#include <cstddef>

// Problem constants (fixed by the reference: T=4096, H=I=2048, E=8, top-2)
#define TTOK 4096
#define HD   2048
#define NE   8
#define NSLOT (2*TTOK)

// GEMM tiling
#define BM 128
#define BN 128
#define BKC 32
#define LDA 40            // 32 + 8 halves pad (16B), conflict-free for ldmatrix
#define LDB 136           // 128 + 8 halves pad
#define ASTAGE (BM*LDA*2) // bytes per A stage
#define BSTAGE (BKC*LDB*2)
#define KB_PER_SEG (HD/BKC)       // 64
#define NSTAGE (3*KB_PER_SEG)     // 192 stages: 3 bf16x3 segments of K=2048

// ---------------- device scratch (static: no allocations allowed) ----------------
__device__ int   g_counts[NE];
__device__ int   g_offs[NE+1];
__device__ int   g_cursor[NE];
__device__ int   g_top_idx[NSLOT];
__device__ float g_top_scale[NSLOT];
__device__ int   g_slot_tok[NSLOT];
__device__ float g_slot_scale[NSLOT];

__device__ __align__(16) __nv_bfloat16 g_xh[(size_t)TTOK*HD];
__device__ __align__(16) __nv_bfloat16 g_xl[(size_t)TTOK*HD];
__device__ __align__(16) __nv_bfloat16 g_w1h[(size_t)NE*HD*HD];
__device__ __align__(16) __nv_bfloat16 g_w1l[(size_t)NE*HD*HD];
__device__ __align__(16) __nv_bfloat16 g_w3h[(size_t)NE*HD*HD];
__device__ __align__(16) __nv_bfloat16 g_w3l[(size_t)NE*HD*HD];
__device__ __align__(16) __nv_bfloat16 g_w2h[(size_t)NE*HD*HD];
__device__ __align__(16) __nv_bfloat16 g_w2l[(size_t)NE*HD*HD];
__device__ __align__(16) float         g_gbuf[(size_t)NSLOT*HD];
__device__ __align__(16) float         g_ubuf[(size_t)NSLOT*HD];
__device__ __align__(16) __nv_bfloat16 g_acth[(size_t)NSLOT*HD];
__device__ __align__(16) __nv_bfloat16 g_actl[(size_t)NSLOT*HD];

// ---------------- small helpers ----------------
__device__ __forceinline__ uint32_t smem_u32(const void* p) {
    return (uint32_t)__cvta_generic_to_shared(p);
}
__device__ __forceinline__ void cp16(uint32_t dst, const void* src, int szbytes) {
    asm volatile("cp.async.cg.shared.global [%0], [%1], 16, %2;\n"
                 :: "r"(dst), "l"(src), "r"(szbytes));
}
__device__ __forceinline__ void cp_commit() {
    asm volatile("cp.async.commit_group;\n");
}
__device__ __forceinline__ void ldsm_x4(uint32_t (&r)[4], uint32_t addr) {
    asm volatile("ldmatrix.sync.aligned.m8n8.x4.shared.b16 {%0,%1,%2,%3}, [%4];\n"
                 : "=r"(r[0]), "=r"(r[1]), "=r"(r[2]), "=r"(r[3]) : "r"(addr));
}
__device__ __forceinline__ void ldsm_x4_t(uint32_t (&r)[4], uint32_t addr) {
    asm volatile("ldmatrix.sync.aligned.m8n8.x4.trans.shared.b16 {%0,%1,%2,%3}, [%4];\n"
                 : "=r"(r[0]), "=r"(r[1]), "=r"(r[2]), "=r"(r[3]) : "r"(addr));
}
__device__ __forceinline__ void mma16816(float (&c)[4], const uint32_t (&a)[4],
                                         uint32_t b0, uint32_t b1) {
    asm volatile(
        "mma.sync.aligned.m16n8k16.row.col.f32.bf16.bf16.f32 "
        "{%0,%1,%2,%3}, {%4,%5,%6,%7}, {%8,%9}, {%0,%1,%2,%3};\n"
        : "+f"(c[0]), "+f"(c[1]), "+f"(c[2]), "+f"(c[3])
        : "r"(a[0]), "r"(a[1]), "r"(a[2]), "r"(a[3]), "r"(b0), "r"(b1));
}

// ---------------- setup kernels ----------------
__global__ void init_small_kernel() {
    int i = threadIdx.x;
    if (i < NE) { g_counts[i] = 0; g_cursor[i] = 0; }
}

// fp32 -> bf16 hi/lo split. W selects destination scratch.
template <int W>
__global__ void cvt_kernel(const float* __restrict__ src) {
    __nv_bfloat16 *dh, *dl;
    size_t n;
    if (W == 0)      { dh = g_xh;  dl = g_xl;  n = (size_t)TTOK*HD; }
    else if (W == 1) { dh = g_w1h; dl = g_w1l; n = (size_t)NE*HD*HD; }
    else if (W == 2) { dh = g_w3h; dl = g_w3l; n = (size_t)NE*HD*HD; }
    else             { dh = g_w2h; dl = g_w2l; n = (size_t)NE*HD*HD; }
    size_t n4 = n >> 2;
    const float4* s4 = (const float4*)src;
    __nv_bfloat162* dh2 = (__nv_bfloat162*)dh;
    __nv_bfloat162* dl2 = (__nv_bfloat162*)dl;
    size_t stride = (size_t)gridDim.x * blockDim.x;
    for (size_t i = (size_t)blockIdx.x * blockDim.x + threadIdx.x; i < n4; i += stride) {
        float4 v = s4[i];
        __nv_bfloat162 h01 = __floats2bfloat162_rn(v.x, v.y);
        __nv_bfloat162 h23 = __floats2bfloat162_rn(v.z, v.w);
        __nv_bfloat162 l01 = __floats2bfloat162_rn(v.x - __low2float(h01),
                                                   v.y - __high2float(h01));
        __nv_bfloat162 l23 = __floats2bfloat162_rn(v.z - __low2float(h23),
                                                   v.w - __high2float(h23));
        dh2[2*i] = h01; dh2[2*i+1] = h23;
        dl2[2*i] = l01; dl2[2*i+1] = l23;
    }
}

// Router: one warp per token. logits = x[t] . rw[:,e]; top-2 + softmax scales.
__global__ void router_kernel(const float* __restrict__ x,
                              const float* __restrict__ rw) {
    int warp = threadIdx.x >> 5;
    int t = blockIdx.x * (blockDim.x >> 5) + warp;
    if (t >= TTOK) return;
    int lane = threadIdx.x & 31;
    float acc[NE];
#pragma unroll
    for (int e = 0; e < NE; e++) acc[e] = 0.f;
    const float* xr = x + (size_t)t * HD;
    for (int h = lane; h < HD; h += 32) {
        float xv = xr[h];
        const float* r = rw + (size_t)h * NE;
#pragma unroll
        for (int e = 0; e < NE; e++) acc[e] = fmaf(xv, r[e], acc[e]);
    }
#pragma unroll
    for (int e = 0; e < NE; e++) {
#pragma unroll
        for (int o = 16; o; o >>= 1) acc[e] += __shfl_xor_sync(0xffffffffu, acc[e], o);
    }
    if (lane == 0) {
        int i0 = 0; float v0 = acc[0];
#pragma unroll
        for (int e = 1; e < NE; e++) if (acc[e] > v0) { v0 = acc[e]; i0 = e; }
        int i1 = -1; float v1 = -3.4e38f;
#pragma unroll
        for (int e = 0; e < NE; e++) if (e != i0 && acc[e] > v1) { v1 = acc[e]; i1 = e; }
        float ex = expf(v1 - v0);
        float inv = 1.f / (1.f + ex);
        g_top_idx[2*t]   = i0; g_top_scale[2*t]   = inv;
        g_top_idx[2*t+1] = i1; g_top_scale[2*t+1] = ex * inv;
        atomicAdd(&g_counts[i0], 1);
        atomicAdd(&g_counts[i1], 1);
    }
}

__global__ void scan_kernel() {
    if (threadIdx.x == 0) {
        int o = 0;
        for (int e = 0; e < NE; e++) { g_offs[e] = o; g_cursor[e] = o; o += g_counts[e]; }
        g_offs[NE] = o;   // == NSLOT always
    }
}

__global__ void scatter_kernel() {
    int i = blockIdx.x * blockDim.x + threadIdx.x;
    if (i < NSLOT) {
        int e = g_top_idx[i];
        int pos = atomicAdd(&g_cursor[e], 1);
        g_slot_tok[pos]   = i >> 1;
        g_slot_scale[pos] = g_top_scale[i];
    }
}

// swiglu + bf16 hi/lo split of the activation
__global__ void swiglu_kernel() {
    size_t n4 = ((size_t)NSLOT * HD) >> 2;
    const float4* g4 = (const float4*)g_gbuf;
    const float4* u4 = (const float4*)g_ubuf;
    __nv_bfloat162* ah2 = (__nv_bfloat162*)g_acth;
    __nv_bfloat162* al2 = (__nv_bfloat162*)g_actl;
    size_t stride = (size_t)gridDim.x * blockDim.x;
    for (size_t i = (size_t)blockIdx.x * blockDim.x + threadIdx.x; i < n4; i += stride) {
        float4 g = g4[i], u = u4[i];
        float a0 = u.x * (g.x / (1.f + __expf(-g.x)));
        float a1 = u.y * (g.y / (1.f + __expf(-g.y)));
        float a2 = u.z * (g.z / (1.f + __expf(-g.z)));
        float a3 = u.w * (g.w / (1.f + __expf(-g.w)));
        __nv_bfloat162 h01 = __floats2bfloat162_rn(a0, a1);
        __nv_bfloat162 h23 = __floats2bfloat162_rn(a2, a3);
        __nv_bfloat162 l01 = __floats2bfloat162_rn(a0 - __low2float(h01),
                                                   a1 - __high2float(h01));
        __nv_bfloat162 l23 = __floats2bfloat162_rn(a2 - __low2float(h23),
                                                   a3 - __high2float(h23));
        ah2[2*i] = h01; ah2[2*i+1] = h23;
        al2[2*i] = l01; al2[2*i+1] = l23;
    }
}

// ---------------- grouped gather-GEMM (bf16x3 emulated fp32) ----------------
// MODE 0: C=gbuf  <- gather(x) @ w1[e]
// MODE 1: C=ubuf  <- gather(x) @ w3[e]
// MODE 2: out    +<- act @ w2[e], scaled atomicAdd scatter to tokens
template <int MODE>
__global__ void __launch_bounds__(256)
gemm_kernel(float* __restrict__ dout) {
    __shared__ __nv_bfloat16 As[2][BM][LDA];
    __shared__ __nv_bfloat16 Bs[2][BKC][LDB];

    const int e = blockIdx.z;
    const int rowBeg = g_offs[e], rowEnd = g_offs[e+1];
    const int row0 = rowBeg + blockIdx.y * BM;
    if (row0 >= rowEnd) return;
    const int n0 = blockIdx.x * BN;

    const __nv_bfloat16* Ah = (MODE == 2) ? g_acth : g_xh;
    const __nv_bfloat16* Al = (MODE == 2) ? g_actl : g_xl;
    const __nv_bfloat16* Bh = ((MODE == 0) ? g_w1h : (MODE == 1) ? g_w3h : g_w2h)
                              + (size_t)e * HD * HD;
    const __nv_bfloat16* Bl = ((MODE == 0) ? g_w1l : (MODE == 1) ? g_w3l : g_w2l)
                              + (size_t)e * HD * HD;

    const int tid = threadIdx.x;

    // A global-load mapping: rows tid/4 and tid/4+64, 16B segment tid%4
    const int ra0 = tid >> 2, segA = tid & 3;
    const __nv_bfloat16* aph[2]; const __nv_bfloat16* apl[2]; int asz[2];
    uint32_t a_sm[2];
#pragma unroll
    for (int i = 0; i < 2; i++) {
        int slot = row0 + ra0 + i * 64;
        bool v = slot < rowEnd;
        int tok = v ? ((MODE == 2) ? slot : g_slot_tok[slot]) : 0;
        aph[i] = Ah + (size_t)tok * HD + segA * 8;
        apl[i] = Al + (size_t)tok * HD + segA * 8;
        asz[i] = v ? 16 : 0;
        a_sm[i] = smem_u32(&As[0][ra0 + i * 64][segA * 8]);
    }
    // B global-load mapping: rows tid/16 and tid/16+16, 16B segment tid%16
    const int rb0 = tid >> 4, segB = tid & 15;
    uint32_t b_sm[2];
    b_sm[0] = smem_u32(&Bs[0][rb0][segB * 8]);
    b_sm[1] = smem_u32(&Bs[0][rb0 + 16][segB * 8]);

    auto load_stage = [&](int it, int buf) {
        int s = it >> 6;            // bf16x3 segment: 0=(Ah,Bh) 1=(Al,Bh) 2=(Ah,Bl)
        int koff = (it & 63) * BKC;
        const __nv_bfloat16* a0 = ((s == 1) ? apl[0] : aph[0]) + koff;
        const __nv_bfloat16* a1 = ((s == 1) ? apl[1] : aph[1]) + koff;
        const __nv_bfloat16* bb = (s == 2) ? Bl : Bh;
        uint32_t ao = (uint32_t)buf * ASTAGE;
        uint32_t bo = (uint32_t)buf * BSTAGE;
        cp16(a_sm[0] + ao, a0, asz[0]);
        cp16(a_sm[1] + ao, a1, asz[1]);
        const __nv_bfloat16* bp0 = bb + (size_t)(koff + rb0) * HD + n0 + segB * 8;
        cp16(b_sm[0] + bo, bp0, 16);
        cp16(b_sm[1] + bo, bp0 + (size_t)16 * HD, 16);
        cp_commit();
    };

    const int wid = tid >> 5, lane = tid & 31;
    const int wm = wid & 3, wn = wid >> 2;     // 4 warps M x 2 warps N
    const int ar = lane & 15, ac = (lane >> 4) * 8;
    const int br = lane & 15, bc = (lane >> 4) * 8;

    float acc[2][8][4];
#pragma unroll
    for (int mt = 0; mt < 2; mt++)
#pragma unroll
        for (int nt = 0; nt < 8; nt++)
#pragma unroll
            for (int q = 0; q < 4; q++) acc[mt][nt][q] = 0.f;

    load_stage(0, 0);
    for (int it = 0; it < NSTAGE; it++) {
        int buf = it & 1;
        if (it + 1 < NSTAGE) {
            load_stage(it + 1, buf ^ 1);
            asm volatile("cp.async.wait_group 1;\n");
        } else {
            asm volatile("cp.async.wait_group 0;\n");
        }
        __syncthreads();
#pragma unroll
        for (int kk = 0; kk < 2; kk++) {
            int k16 = kk * 16;
            uint32_t a[2][4];
#pragma unroll
            for (int mt = 0; mt < 2; mt++)
                ldsm_x4(a[mt], smem_u32(&As[buf][wm * 32 + mt * 16 + ar][k16 + ac]));
#pragma unroll
            for (int p = 0; p < 4; p++) {
                uint32_t b[4];
                ldsm_x4_t(b, smem_u32(&Bs[buf][k16 + br][wn * 64 + p * 16 + bc]));
                mma16816(acc[0][2*p],   a[0], b[0], b[1]);
                mma16816(acc[0][2*p+1], a[0], b[2], b[3]);
                mma16816(acc[1][2*p],   a[1], b[0], b[1]);
                mma16816(acc[1][2*p+1], a[1], b[2], b[3]);
            }
        }
        __syncthreads();
    }

    // epilogue
    const int rIn = lane >> 2, cIn = (lane & 3) * 2;
#pragma unroll
    for (int mt = 0; mt < 2; mt++) {
#pragma unroll
        for (int half = 0; half < 2; half++) {
            int slot = row0 + wm * 32 + mt * 16 + rIn + half * 8;
            if (slot < rowEnd) {
                if (MODE < 2) {
                    float* Cb = ((MODE == 1) ? g_ubuf : g_gbuf)
                                + (size_t)slot * HD + n0 + wn * 64 + cIn;
#pragma unroll
                    for (int nt = 0; nt < 8; nt++) {
                        float2 v = make_float2(acc[mt][nt][half*2], acc[mt][nt][half*2+1]);
                        *(float2*)(Cb + nt * 8) = v;
                    }
                } else {
                    int tok = g_slot_tok[slot];
                    float sc = g_slot_scale[slot];
                    float* Cb = dout + (size_t)tok * HD + n0 + wn * 64 + cIn;
#pragma unroll
                    for (int nt = 0; nt < 8; nt++) {
                        atomicAdd(Cb + nt * 8,     sc * acc[mt][nt][half*2]);
                        atomicAdd(Cb + nt * 8 + 1, sc * acc[mt][nt][half*2+1]);
                    }
                }
            }
        }
    }
}

// ---------------- host launcher ----------------
extern "C" void kernel_launch(void* const* d_in, const int* in_sizes, int n_in,
                              void* d_out, int out_size) {
    const float* x  = (const float*)d_in[0];
    const float* rw = (const float*)d_in[1];
    const float* w1 = (const float*)d_in[2];
    const float* w3 = (const float*)d_in[3];
    const float* w2 = (const float*)d_in[4];
    float* out = (float*)d_out;

    cudaMemsetAsync(out, 0, (size_t)out_size * sizeof(float), 0);
    init_small_kernel<<<1, 32>>>();

    cvt_kernel<0><<<1024, 256>>>(x);
    cvt_kernel<1><<<4096, 256>>>(w1);
    cvt_kernel<2><<<4096, 256>>>(w3);
    cvt_kernel<3><<<4096, 256>>>(w2);

    router_kernel<<<TTOK / 8, 256>>>(x, rw);
    scan_kernel<<<1, 32>>>();
    scatter_kernel<<<NSLOT / 256, 256>>>();

    dim3 gg(HD / BN, (TTOK + BM - 1) / BM, NE);
    gemm_kernel<0><<<gg, 256>>>(nullptr);   // gate
    gemm_kernel<1><<<gg, 256>>>(nullptr);   // up
    swiglu_kernel<<<2048, 256>>>();
    gemm_kernel<2><<<gg, 256>>>(out);       // down + combine
}

// round 3
// speedup vs baseline: 1.5802x; 1.5802x over previous
#include <cuda_runtime.h>
#include <cuda_fp16.h>
#include <cstdint>
#include <cstddef>

// Problem constants: T=4096, H=I=2048, E=8, top-2
#define TTOK 4096
#define HD   2048
#define NE   8
#define NSLOT (2*TTOK)

// GEMM tiling: CTA 128(M) x 256(N), K-chunk 32, 4-stage cp.async ring, 512 thr
#define BM 128
#define BN 256
#define BKC 32
#define NCHUNK (HD/BKC)     // 64
#define NSTG 4

// smem byte offsets within one stage
#define AH_B 0              // A-hi: 128 rows x 40 halves = 10240 B (row stride 80B, 16B-aligned)
#define AL_B 10240          // A-lo: 10240 B
#define BB_B 20480          // B   : 32 rows x 264 halves = 16896 B (row stride 528B)
#define STG_B 37376
#define DYN_SMEM (NSTG*STG_B)   // 149504 B

// ---------------- device scratch ----------------
__device__ int   g_counts[NE];
__device__ int   g_offs[NE+1];
__device__ int   g_cursor[NE];
__device__ int   g_top_idx[NSLOT];
__device__ float g_top_scale[NSLOT];
__device__ int   g_slot_tok[NSLOT];
__device__ int   g_tok_pos[NSLOT];

__device__ __align__(16) __half g_xh[(size_t)TTOK*HD];
__device__ __align__(16) __half g_xl[(size_t)TTOK*HD];
__device__ __align__(16) __half g_w1[(size_t)NE*HD*HD];   // [e][k][n] fp16
__device__ __align__(16) __half g_w3[(size_t)NE*HD*HD];
__device__ __align__(16) __half g_w2[(size_t)NE*HD*HD];
__device__ __align__(16) float  g_gbuf[(size_t)NSLOT*HD];
__device__ __align__(16) float  g_ubuf[(size_t)NSLOT*HD];
__device__ __align__(16) __half g_acth[(size_t)NSLOT*HD];
__device__ __align__(16) __half g_actl[(size_t)NSLOT*HD];

// ---------------- helpers ----------------
__device__ __forceinline__ uint32_t smem_u32(const void* p) {
    return (uint32_t)__cvta_generic_to_shared(p);
}
__device__ __forceinline__ void cp16(uint32_t dst, const void* src, int szbytes) {
    asm volatile("cp.async.cg.shared.global [%0], [%1], 16, %2;\n"
                 :: "r"(dst), "l"(src), "r"(szbytes));
}
__device__ __forceinline__ void cp_commit() {
    asm volatile("cp.async.commit_group;\n");
}
__device__ __forceinline__ void wait_n(int n) {
    if (n >= 2)      asm volatile("cp.async.wait_group 2;\n" ::: "memory");
    else if (n == 1) asm volatile("cp.async.wait_group 1;\n" ::: "memory");
    else             asm volatile("cp.async.wait_group 0;\n" ::: "memory");
}
__device__ __forceinline__ void ldsm_x4(uint32_t (&r)[4], uint32_t addr) {
    asm volatile("ldmatrix.sync.aligned.m8n8.x4.shared.b16 {%0,%1,%2,%3}, [%4];\n"
                 : "=r"(r[0]), "=r"(r[1]), "=r"(r[2]), "=r"(r[3]) : "r"(addr));
}
__device__ __forceinline__ void ldsm_x4_t(uint32_t (&r)[4], uint32_t addr) {
    asm volatile("ldmatrix.sync.aligned.m8n8.x4.trans.shared.b16 {%0,%1,%2,%3}, [%4];\n"
                 : "=r"(r[0]), "=r"(r[1]), "=r"(r[2]), "=r"(r[3]) : "r"(addr));
}
__device__ __forceinline__ void mma16816(float (&c)[4], const uint32_t (&a)[4],
                                         uint32_t b0, uint32_t b1) {
    asm volatile(
        "mma.sync.aligned.m16n8k16.row.col.f32.f16.f16.f32 "
        "{%0,%1,%2,%3}, {%4,%5,%6,%7}, {%8,%9}, {%0,%1,%2,%3};\n"
        : "+f"(c[0]), "+f"(c[1]), "+f"(c[2]), "+f"(c[3])
        : "r"(a[0]), "r"(a[1]), "r"(a[2]), "r"(a[3]), "r"(b0), "r"(b1));
}

// ---------------- setup kernels ----------------
__global__ void init_small_kernel() {
    int i = threadIdx.x;
    if (i < NE) { g_counts[i] = 0; g_cursor[i] = 0; }
}

// x: fp32 -> fp16 hi/lo
__global__ void cvt_x_kernel(const float* __restrict__ src) {
    size_t n4 = ((size_t)TTOK * HD) >> 2;
    const float4* s4 = (const float4*)src;
    __half2* dh2 = (__half2*)g_xh;
    __half2* dl2 = (__half2*)g_xl;
    size_t stride = (size_t)gridDim.x * blockDim.x;
    for (size_t i = (size_t)blockIdx.x * blockDim.x + threadIdx.x; i < n4; i += stride) {
        float4 v = s4[i];
        __half2 h01 = __floats2half2_rn(v.x, v.y);
        __half2 h23 = __floats2half2_rn(v.z, v.w);
        __half2 l01 = __floats2half2_rn(v.x - __low2float(h01), v.y - __high2float(h01));
        __half2 l23 = __floats2half2_rn(v.z - __low2float(h23), v.w - __high2float(h23));
        dh2[2*i] = h01; dh2[2*i+1] = h23;
        dl2[2*i] = l01; dl2[2*i+1] = l23;
    }
}

// weights: fp32 -> fp16 (single copy, layout unchanged [e][k][n])
template <int W>
__global__ void cvt_w_kernel(const float* __restrict__ src) {
    __half* d = (W == 0) ? g_w1 : (W == 1) ? g_w3 : g_w2;
    size_t n4 = ((size_t)NE * HD * HD) >> 2;
    const float4* s4 = (const float4*)src;
    __half2* d2 = (__half2*)d;
    size_t stride = (size_t)gridDim.x * blockDim.x;
    for (size_t i = (size_t)blockIdx.x * blockDim.x + threadIdx.x; i < n4; i += stride) {
        float4 v = s4[i];
        d2[2*i]   = __floats2half2_rn(v.x, v.y);
        d2[2*i+1] = __floats2half2_rn(v.z, v.w);
    }
}

// Router: one warp per token
__global__ void router_kernel(const float* __restrict__ x,
                              const float* __restrict__ rw) {
    int warp = threadIdx.x >> 5;
    int t = blockIdx.x * (blockDim.x >> 5) + warp;
    if (t >= TTOK) return;
    int lane = threadIdx.x & 31;
    float acc[NE];
#pragma unroll
    for (int e = 0; e < NE; e++) acc[e] = 0.f;
    const float* xr = x + (size_t)t * HD;
    for (int h = lane; h < HD; h += 32) {
        float xv = xr[h];
        const float* r = rw + (size_t)h * NE;
#pragma unroll
        for (int e = 0; e < NE; e++) acc[e] = fmaf(xv, r[e], acc[e]);
    }
#pragma unroll
    for (int e = 0; e < NE; e++) {
#pragma unroll
        for (int o = 16; o; o >>= 1) acc[e] += __shfl_xor_sync(0xffffffffu, acc[e], o);
    }
    if (lane == 0) {
        int i0 = 0; float v0 = acc[0];
#pragma unroll
        for (int e = 1; e < NE; e++) if (acc[e] > v0) { v0 = acc[e]; i0 = e; }
        int i1 = -1; float v1 = -3.4e38f;
#pragma unroll
        for (int e = 0; e < NE; e++) if (e != i0 && acc[e] > v1) { v1 = acc[e]; i1 = e; }
        float ex = expf(v1 - v0);
        float inv = 1.f / (1.f + ex);
        g_top_idx[2*t]   = i0; g_top_scale[2*t]   = inv;
        g_top_idx[2*t+1] = i1; g_top_scale[2*t+1] = ex * inv;
        atomicAdd(&g_counts[i0], 1);
        atomicAdd(&g_counts[i1], 1);
    }
}

__global__ void scan_kernel() {
    if (threadIdx.x == 0) {
        int o = 0;
        for (int e = 0; e < NE; e++) { g_offs[e] = o; g_cursor[e] = o; o += g_counts[e]; }
        g_offs[NE] = o;
    }
}

__global__ void scatter_kernel() {
    int i = blockIdx.x * blockDim.x + threadIdx.x;
    if (i < NSLOT) {
        int e = g_top_idx[i];
        int pos = atomicAdd(&g_cursor[e], 1);
        g_slot_tok[pos] = i >> 1;
        g_tok_pos[i] = pos;
    }
}

// swiglu + fp16 hi/lo split
__global__ void swiglu_kernel() {
    size_t n4 = ((size_t)NSLOT * HD) >> 2;
    const float4* g4 = (const float4*)g_gbuf;
    const float4* u4 = (const float4*)g_ubuf;
    __half2* ah2 = (__half2*)g_acth;
    __half2* al2 = (__half2*)g_actl;
    size_t stride = (size_t)gridDim.x * blockDim.x;
    for (size_t i = (size_t)blockIdx.x * blockDim.x + threadIdx.x; i < n4; i += stride) {
        float4 g = g4[i], u = u4[i];
        float a0 = u.x * (g.x / (1.f + __expf(-g.x)));
        float a1 = u.y * (g.y / (1.f + __expf(-g.y)));
        float a2 = u.z * (g.z / (1.f + __expf(-g.z)));
        float a3 = u.w * (g.w / (1.f + __expf(-g.w)));
        __half2 h01 = __floats2half2_rn(a0, a1);
        __half2 h23 = __floats2half2_rn(a2, a3);
        __half2 l01 = __floats2half2_rn(a0 - __low2float(h01), a1 - __high2float(h01));
        __half2 l23 = __floats2half2_rn(a2 - __low2float(h23), a3 - __high2float(h23));
        ah2[2*i] = h01; ah2[2*i+1] = h23;
        al2[2*i] = l01; al2[2*i+1] = l23;
    }
}

// combine: out[t] = s0*down[pos0] + s1*down[pos1]
__global__ void combine_kernel(float* __restrict__ out) {
    int i = blockIdx.x * blockDim.x + threadIdx.x;
    int t  = i >> 9;           // HD/4 = 512 float4 per token
    int h4 = i & 511;
    float s0 = g_top_scale[2*t], s1 = g_top_scale[2*t+1];
    int p0 = g_tok_pos[2*t], p1 = g_tok_pos[2*t+1];
    float4 a = ((const float4*)(g_gbuf + (size_t)p0 * HD))[h4];
    float4 b = ((const float4*)(g_gbuf + (size_t)p1 * HD))[h4];
    float4 o;
    o.x = s0*a.x + s1*b.x; o.y = s0*a.y + s1*b.y;
    o.z = s0*a.z + s1*b.z; o.w = s0*a.w + s1*b.w;
    ((float4*)(out + (size_t)t * HD))[h4] = o;
}

// ---------------- grouped gather-GEMM, fp16x2 (A split hi/lo, B single fp16) ----------------
// MODE 0: gate+up  (A = gathered x; blockIdx.x < 8 -> w1/gbuf, >= 8 -> w3/ubuf)
// MODE 1: down     (A = act slots; B = w2; C = gbuf)
template <int MODE>
__global__ void __launch_bounds__(512, 1)
gemm_fp16x2() {
    extern __shared__ __align__(128) char sm[];
    const int e = blockIdx.z;
    const int rowBeg = g_offs[e], rowEnd = g_offs[e+1];
    const int row0 = rowBeg + blockIdx.y * BM;
    if (row0 >= rowEnd) return;

    const int xb = blockIdx.x;
    const __half *Ah, *Al, *Bw;
    float* Cb;
    int n0;
    if (MODE == 0) {
        bool up = xb >= (HD/BN);
        n0 = (xb & (HD/BN - 1)) * BN;
        Ah = g_xh; Al = g_xl;
        Bw = (up ? g_w3 : g_w1) + (size_t)e * HD * HD;
        Cb = up ? g_ubuf : g_gbuf;
    } else {
        n0 = xb * BN;
        Ah = g_acth; Al = g_actl;
        Bw = g_w2 + (size_t)e * HD * HD;
        Cb = g_gbuf;
    }

    const int tid = threadIdx.x;
    const uint32_t sb = smem_u32(sm);

    // ---- load mappings ----
    // A: 512 threads -> 128 rows x 4 x 16B segments
    const int arow = tid >> 2, aseg = tid & 3;
    const int aslot = row0 + arow;
    const bool av = aslot < rowEnd;
    const int tok = av ? ((MODE == 0) ? g_slot_tok[aslot] : aslot) : 0;
    const __half* aSrcH = Ah + (size_t)tok * HD + aseg * 8;
    const __half* aSrcL = Al + (size_t)tok * HD + aseg * 8;
    const int asz = av ? 16 : 0;
    const uint32_t aDst = (uint32_t)(arow * 80 + aseg * 16);
    // B: 2 x (512 threads) -> 32 k-rows x 32 x 16B segments
    const int bk = tid >> 5, bseg = tid & 31;
    const __half* bSrc = Bw + (size_t)bk * HD + n0 + bseg * 8;
    const uint32_t bDst = (uint32_t)(bk * 528 + bseg * 16);

    auto load_stage = [&](int c, int stg) {
        uint32_t st = sb + (uint32_t)stg * STG_B;
        size_t k0 = (size_t)c * BKC;
        cp16(st + AH_B + aDst, aSrcH + k0, asz);
        cp16(st + AL_B + aDst, aSrcL + k0, asz);
        const __half* bp = bSrc + k0 * HD;
        cp16(st + BB_B + bDst, bp, 16);
        cp16(st + BB_B + bDst + 16 * 528, bp + (size_t)16 * HD, 16);
        cp_commit();
    };

    const int wid = tid >> 5, lane = tid & 31;
    const int wm = wid & 3, wn = wid >> 2;        // 4 warps M x 4 warps N, warp tile 32x64
    const int ar = lane & 15, ac = (lane >> 4) * 8;
    const int br = lane & 15, bc = (lane >> 4) * 8;

    float acc[2][8][4];
#pragma unroll
    for (int mt = 0; mt < 2; mt++)
#pragma unroll
        for (int nt = 0; nt < 8; nt++)
#pragma unroll
            for (int q = 0; q < 4; q++) acc[mt][nt][q] = 0.f;

    load_stage(0, 0);
    load_stage(1, 1);
    load_stage(2, 2);

    for (int c = 0; c < NCHUNK; c++) {
        int rem = NCHUNK - 1 - c;
        wait_n(rem >= 2 ? 2 : rem);
        __syncthreads();
        if (c + 3 < NCHUNK) load_stage(c + 3, (c + 3) & 3);
        uint32_t stb = sb + (uint32_t)(c & 3) * STG_B;

#pragma unroll
        for (int kk = 0; kk < 2; kk++) {
            uint32_t a_h[2][4], a_l[2][4];
#pragma unroll
            for (int mt = 0; mt < 2; mt++) {
                uint32_t aaddr = stb + AH_B
                    + (uint32_t)((wm * 32 + mt * 16 + ar) * 80 + (kk * 16 + ac) * 2);
                ldsm_x4(a_h[mt], aaddr);
                ldsm_x4(a_l[mt], aaddr + (AL_B - AH_B));
            }
#pragma unroll
            for (int p = 0; p < 4; p++) {
                uint32_t b[4];
                uint32_t baddr = stb + BB_B
                    + (uint32_t)((kk * 16 + br) * 528 + (wn * 64 + p * 16 + bc) * 2);
                ldsm_x4_t(b, baddr);
                mma16816(acc[0][2*p],   a_h[0], b[0], b[1]);
                mma16816(acc[0][2*p+1], a_h[0], b[2], b[3]);
                mma16816(acc[1][2*p],   a_h[1], b[0], b[1]);
                mma16816(acc[1][2*p+1], a_h[1], b[2], b[3]);
                mma16816(acc[0][2*p],   a_l[0], b[0], b[1]);
                mma16816(acc[0][2*p+1], a_l[0], b[2], b[3]);
                mma16816(acc[1][2*p],   a_l[1], b[0], b[1]);
                mma16816(acc[1][2*p+1], a_l[1], b[2], b[3]);
            }
        }
    }

    // ---- epilogue ----
    const int rIn = lane >> 2, cIn = (lane & 3) * 2;
#pragma unroll
    for (int mt = 0; mt < 2; mt++) {
#pragma unroll
        for (int half = 0; half < 2; half++) {
            int slot = row0 + wm * 32 + mt * 16 + rIn + half * 8;
            if (slot < rowEnd) {
                float* Cp = Cb + (size_t)slot * HD + n0 + wn * 64 + cIn;
#pragma unroll
                for (int nt = 0; nt < 8; nt++) {
                    float2 v = make_float2(acc[mt][nt][half*2], acc[mt][nt][half*2+1]);
                    *(float2*)(Cp + nt * 8) = v;
                }
            }
        }
    }
}

// ---------------- host launcher ----------------
extern "C" void kernel_launch(void* const* d_in, const int* in_sizes, int n_in,
                              void* d_out, int out_size) {
    const float* x  = (const float*)d_in[0];
    const float* rw = (const float*)d_in[1];
    const float* w1 = (const float*)d_in[2];
    const float* w3 = (const float*)d_in[3];
    const float* w2 = (const float*)d_in[4];
    float* out = (float*)d_out;

    cudaFuncSetAttribute(gemm_fp16x2<0>, cudaFuncAttributeMaxDynamicSharedMemorySize, DYN_SMEM);
    cudaFuncSetAttribute(gemm_fp16x2<1>, cudaFuncAttributeMaxDynamicSharedMemorySize, DYN_SMEM);

    init_small_kernel<<<1, 32>>>();

    cvt_x_kernel<<<1024, 256>>>(x);
    cvt_w_kernel<0><<<4096, 256>>>(w1);
    cvt_w_kernel<1><<<4096, 256>>>(w3);
    cvt_w_kernel<2><<<4096, 256>>>(w2);

    router_kernel<<<TTOK / 8, 256>>>(x, rw);
    scan_kernel<<<1, 32>>>();
    scatter_kernel<<<NSLOT / 256, 256>>>();

    // gate+up fused launch: x = 16 (8 gate N-tiles + 8 up N-tiles)
    dim3 ggu(2 * (HD/BN), NSLOT/BM, NE);
    gemm_fp16x2<0><<<ggu, 512, DYN_SMEM>>>();

    swiglu_kernel<<<2048, 256>>>();

    dim3 gd(HD/BN, NSLOT/BM, NE);
    gemm_fp16x2<1><<<gd, 512, DYN_SMEM>>>();

    combine_kernel<<<(TTOK * HD / 4) / 256, 256>>>(out);
}

// round 4
// speedup vs baseline: 2.3166x; 1.4660x over previous
#include <cuda_runtime.h>
#include <cuda_fp16.h>
#include <cstdint>
#include <cstddef>

// Problem constants: T=4096, H=I=2048, E=8, top-2
#define TTOK 4096
#define HD   2048
#define NE   8
#define NSLOT (2*TTOK)

// GEMM tiling: CTA 128(M) x 256(N), K-chunk 32, 4-stage cp.async ring, 512 thr
#define BM 128
#define BN 256
#define BKC 32
#define NCHUNK (HD/BKC)     // 64
#define NSTG 4

// smem byte offsets within one stage
#define AA_B 0              // A: 128 rows x 40 halves = 10240 B (row stride 80B)
#define BB_B 10240          // B: 32 rows x 264 halves = 16896 B (row stride 528B)
#define STG_B 27136
#define DYN_SMEM (NSTG*STG_B)   // 108544 B

// ---------------- device scratch ----------------
__device__ int   g_counts[NE];
__device__ int   g_offs[NE+1];
__device__ int   g_cursor[NE];
__device__ int   g_top_idx[NSLOT];
__device__ float g_top_scale[NSLOT];
__device__ int   g_slot_tok[NSLOT];
__device__ int   g_tok_pos[NSLOT];

__device__ __align__(16) __half g_x16[(size_t)TTOK*HD];
__device__ __align__(16) __half g_w1[(size_t)NE*HD*HD];   // [e][k][n] fp16
__device__ __align__(16) __half g_w3[(size_t)NE*HD*HD];
__device__ __align__(16) __half g_w2[(size_t)NE*HD*HD];
__device__ __align__(16) float  g_gbuf[(size_t)NSLOT*HD];
__device__ __align__(16) float  g_ubuf[(size_t)NSLOT*HD];
__device__ __align__(16) __half g_act[(size_t)NSLOT*HD];

// ---------------- helpers ----------------
__device__ __forceinline__ uint32_t smem_u32(const void* p) {
    return (uint32_t)__cvta_generic_to_shared(p);
}
__device__ __forceinline__ void cp16(uint32_t dst, const void* src, int szbytes) {
    asm volatile("cp.async.cg.shared.global [%0], [%1], 16, %2;\n"
                 :: "r"(dst), "l"(src), "r"(szbytes));
}
__device__ __forceinline__ void cp_commit() {
    asm volatile("cp.async.commit_group;\n");
}
__device__ __forceinline__ void wait_n(int n) {
    if (n >= 2)      asm volatile("cp.async.wait_group 2;\n" ::: "memory");
    else if (n == 1) asm volatile("cp.async.wait_group 1;\n" ::: "memory");
    else             asm volatile("cp.async.wait_group 0;\n" ::: "memory");
}
__device__ __forceinline__ void ldsm_x4(uint32_t (&r)[4], uint32_t addr) {
    asm volatile("ldmatrix.sync.aligned.m8n8.x4.shared.b16 {%0,%1,%2,%3}, [%4];\n"
                 : "=r"(r[0]), "=r"(r[1]), "=r"(r[2]), "=r"(r[3]) : "r"(addr));
}
__device__ __forceinline__ void ldsm_x4_t(uint32_t (&r)[4], uint32_t addr) {
    asm volatile("ldmatrix.sync.aligned.m8n8.x4.trans.shared.b16 {%0,%1,%2,%3}, [%4];\n"
                 : "=r"(r[0]), "=r"(r[1]), "=r"(r[2]), "=r"(r[3]) : "r"(addr));
}
__device__ __forceinline__ void mma16816(float (&c)[4], const uint32_t (&a)[4],
                                         uint32_t b0, uint32_t b1) {
    asm volatile(
        "mma.sync.aligned.m16n8k16.row.col.f32.f16.f16.f32 "
        "{%0,%1,%2,%3}, {%4,%5,%6,%7}, {%8,%9}, {%0,%1,%2,%3};\n"
        : "+f"(c[0]), "+f"(c[1]), "+f"(c[2]), "+f"(c[3])
        : "r"(a[0]), "r"(a[1]), "r"(a[2]), "r"(a[3]), "r"(b0), "r"(b1));
}

// ---------------- setup kernels ----------------
__global__ void init_small_kernel() {
    int i = threadIdx.x;
    if (i < NE) { g_counts[i] = 0; g_cursor[i] = 0; }
}

// x: fp32 -> fp16
__global__ void cvt_x_kernel(const float* __restrict__ src) {
    size_t n4 = ((size_t)TTOK * HD) >> 2;
    const float4* s4 = (const float4*)src;
    __half2* d2 = (__half2*)g_x16;
    size_t stride = (size_t)gridDim.x * blockDim.x;
    for (size_t i = (size_t)blockIdx.x * blockDim.x + threadIdx.x; i < n4; i += stride) {
        float4 v = s4[i];
        d2[2*i]   = __floats2half2_rn(v.x, v.y);
        d2[2*i+1] = __floats2half2_rn(v.z, v.w);
    }
}

// weights: fp32 -> fp16 (layout unchanged [e][k][n])
template <int W>
__global__ void cvt_w_kernel(const float* __restrict__ src) {
    __half* d = (W == 0) ? g_w1 : (W == 1) ? g_w3 : g_w2;
    size_t n4 = ((size_t)NE * HD * HD) >> 2;
    const float4* s4 = (const float4*)src;
    __half2* d2 = (__half2*)d;
    size_t stride = (size_t)gridDim.x * blockDim.x;
    for (size_t i = (size_t)blockIdx.x * blockDim.x + threadIdx.x; i < n4; i += stride) {
        float4 v = s4[i];
        d2[2*i]   = __floats2half2_rn(v.x, v.y);
        d2[2*i+1] = __floats2half2_rn(v.z, v.w);
    }
}

// Router: one warp per token
__global__ void router_kernel(const float* __restrict__ x,
                              const float* __restrict__ rw) {
    int warp = threadIdx.x >> 5;
    int t = blockIdx.x * (blockDim.x >> 5) + warp;
    if (t >= TTOK) return;
    int lane = threadIdx.x & 31;
    float acc[NE];
#pragma unroll
    for (int e = 0; e < NE; e++) acc[e] = 0.f;
    const float* xr = x + (size_t)t * HD;
    for (int h = lane; h < HD; h += 32) {
        float xv = xr[h];
        const float* r = rw + (size_t)h * NE;
#pragma unroll
        for (int e = 0; e < NE; e++) acc[e] = fmaf(xv, r[e], acc[e]);
    }
#pragma unroll
    for (int e = 0; e < NE; e++) {
#pragma unroll
        for (int o = 16; o; o >>= 1) acc[e] += __shfl_xor_sync(0xffffffffu, acc[e], o);
    }
    if (lane == 0) {
        int i0 = 0; float v0 = acc[0];
#pragma unroll
        for (int e = 1; e < NE; e++) if (acc[e] > v0) { v0 = acc[e]; i0 = e; }
        int i1 = -1; float v1 = -3.4e38f;
#pragma unroll
        for (int e = 0; e < NE; e++) if (e != i0 && acc[e] > v1) { v1 = acc[e]; i1 = e; }
        float ex = expf(v1 - v0);
        float inv = 1.f / (1.f + ex);
        g_top_idx[2*t]   = i0; g_top_scale[2*t]   = inv;
        g_top_idx[2*t+1] = i1; g_top_scale[2*t+1] = ex * inv;
        atomicAdd(&g_counts[i0], 1);
        atomicAdd(&g_counts[i1], 1);
    }
}

__global__ void scan_kernel() {
    if (threadIdx.x == 0) {
        int o = 0;
        for (int e = 0; e < NE; e++) { g_offs[e] = o; g_cursor[e] = o; o += g_counts[e]; }
        g_offs[NE] = o;
    }
}

__global__ void scatter_kernel() {
    int i = blockIdx.x * blockDim.x + threadIdx.x;
    if (i < NSLOT) {
        int e = g_top_idx[i];
        int pos = atomicAdd(&g_cursor[e], 1);
        g_slot_tok[pos] = i >> 1;
        g_tok_pos[i] = pos;
    }
}

// swiglu -> fp16 activation
__global__ void swiglu_kernel() {
    size_t n4 = ((size_t)NSLOT * HD) >> 2;
    const float4* g4 = (const float4*)g_gbuf;
    const float4* u4 = (const float4*)g_ubuf;
    __half2* a2 = (__half2*)g_act;
    size_t stride = (size_t)gridDim.x * blockDim.x;
    for (size_t i = (size_t)blockIdx.x * blockDim.x + threadIdx.x; i < n4; i += stride) {
        float4 g = g4[i], u = u4[i];
        float a0 = u.x * (g.x / (1.f + __expf(-g.x)));
        float a1 = u.y * (g.y / (1.f + __expf(-g.y)));
        float a2v = u.z * (g.z / (1.f + __expf(-g.z)));
        float a3 = u.w * (g.w / (1.f + __expf(-g.w)));
        a2[2*i]   = __floats2half2_rn(a0, a1);
        a2[2*i+1] = __floats2half2_rn(a2v, a3);
    }
}

// combine: out[t] = s0*down[pos0] + s1*down[pos1]
__global__ void combine_kernel(float* __restrict__ out) {
    int i = blockIdx.x * blockDim.x + threadIdx.x;
    int t  = i >> 9;           // HD/4 = 512 float4 per token
    int h4 = i & 511;
    float s0 = g_top_scale[2*t], s1 = g_top_scale[2*t+1];
    int p0 = g_tok_pos[2*t], p1 = g_tok_pos[2*t+1];
    float4 a = ((const float4*)(g_gbuf + (size_t)p0 * HD))[h4];
    float4 b = ((const float4*)(g_gbuf + (size_t)p1 * HD))[h4];
    float4 o;
    o.x = s0*a.x + s1*b.x; o.y = s0*a.y + s1*b.y;
    o.z = s0*a.z + s1*b.z; o.w = s0*a.w + s1*b.w;
    ((float4*)(out + (size_t)t * HD))[h4] = o;
}

// ---------------- grouped gather-GEMM, pure fp16, f32 accumulate ----------------
// MODE 0: gate+up  (A = gathered x; blockIdx.x < 8 -> w1/gbuf, >= 8 -> w3/ubuf)
// MODE 1: down     (A = act slots; B = w2; C = gbuf)
template <int MODE>
__global__ void __launch_bounds__(512, 1)
gemm_fp16() {
    extern __shared__ __align__(128) char sm[];
    const int e = blockIdx.z;
    const int rowBeg = g_offs[e], rowEnd = g_offs[e+1];
    const int row0 = rowBeg + blockIdx.y * BM;
    if (row0 >= rowEnd) return;

    const int xb = blockIdx.x;
    const __half *Aw, *Bw;
    float* Cb;
    int n0;
    if (MODE == 0) {
        bool up = xb >= (HD/BN);
        n0 = (xb & (HD/BN - 1)) * BN;
        Aw = g_x16;
        Bw = (up ? g_w3 : g_w1) + (size_t)e * HD * HD;
        Cb = up ? g_ubuf : g_gbuf;
    } else {
        n0 = xb * BN;
        Aw = g_act;
        Bw = g_w2 + (size_t)e * HD * HD;
        Cb = g_gbuf;
    }

    const int tid = threadIdx.x;
    const uint32_t sb = smem_u32(sm);

    // ---- load mappings ----
    // A: 512 threads -> 128 rows x 4 x 16B segments
    const int arow = tid >> 2, aseg = tid & 3;
    const int aslot = row0 + arow;
    const bool av = aslot < rowEnd;
    const int tok = av ? ((MODE == 0) ? g_slot_tok[aslot] : aslot) : 0;
    const __half* aSrc = Aw + (size_t)tok * HD + aseg * 8;
    const int asz = av ? 16 : 0;
    const uint32_t aDst = (uint32_t)(arow * 80 + aseg * 16);
    // B: 2 x (512 threads) -> 32 k-rows x 32 x 16B segments
    const int bk = tid >> 5, bseg = tid & 31;
    const __half* bSrc = Bw + (size_t)bk * HD + n0 + bseg * 8;
    const uint32_t bDst = (uint32_t)(bk * 528 + bseg * 16);

    auto load_stage = [&](int c, int stg) {
        uint32_t st = sb + (uint32_t)stg * STG_B;
        size_t k0 = (size_t)c * BKC;
        cp16(st + AA_B + aDst, aSrc + k0, asz);
        const __half* bp = bSrc + k0 * HD;
        cp16(st + BB_B + bDst, bp, 16);
        cp16(st + BB_B + bDst + 16 * 528, bp + (size_t)16 * HD, 16);
        cp_commit();
    };

    const int wid = tid >> 5, lane = tid & 31;
    const int wm = wid & 3, wn = wid >> 2;        // 4 warps M x 4 warps N, warp tile 32x64
    const int ar = lane & 15, ac = (lane >> 4) * 8;
    const int br = lane & 15, bc = (lane >> 4) * 8;

    float acc[2][8][4];
#pragma unroll
    for (int mt = 0; mt < 2; mt++)
#pragma unroll
        for (int nt = 0; nt < 8; nt++)
#pragma unroll
            for (int q = 0; q < 4; q++) acc[mt][nt][q] = 0.f;

    load_stage(0, 0);
    load_stage(1, 1);
    load_stage(2, 2);

    for (int c = 0; c < NCHUNK; c++) {
        int rem = NCHUNK - 1 - c;
        wait_n(rem >= 2 ? 2 : rem);
        __syncthreads();
        if (c + 3 < NCHUNK) load_stage(c + 3, (c + 3) & 3);
        uint32_t stb = sb + (uint32_t)(c & 3) * STG_B;

#pragma unroll
        for (int kk = 0; kk < 2; kk++) {
            uint32_t a[2][4];
#pragma unroll
            for (int mt = 0; mt < 2; mt++) {
                uint32_t aaddr = stb + AA_B
                    + (uint32_t)((wm * 32 + mt * 16 + ar) * 80 + (kk * 16 + ac) * 2);
                ldsm_x4(a[mt], aaddr);
            }
#pragma unroll
            for (int p = 0; p < 4; p++) {
                uint32_t b[4];
                uint32_t baddr = stb + BB_B
                    + (uint32_t)((kk * 16 + br) * 528 + (wn * 64 + p * 16 + bc) * 2);
                ldsm_x4_t(b, baddr);
                mma16816(acc[0][2*p],   a[0], b[0], b[1]);
                mma16816(acc[0][2*p+1], a[0], b[2], b[3]);
                mma16816(acc[1][2*p],   a[1], b[0], b[1]);
                mma16816(acc[1][2*p+1], a[1], b[2], b[3]);
            }
        }
    }

    // ---- epilogue ----
    const int rIn = lane >> 2, cIn = (lane & 3) * 2;
#pragma unroll
    for (int mt = 0; mt < 2; mt++) {
#pragma unroll
        for (int half = 0; half < 2; half++) {
            int slot = row0 + wm * 32 + mt * 16 + rIn + half * 8;
            if (slot < rowEnd) {
                float* Cp = Cb + (size_t)slot * HD + n0 + wn * 64 + cIn;
#pragma unroll
                for (int nt = 0; nt < 8; nt++) {
                    float2 v = make_float2(acc[mt][nt][half*2], acc[mt][nt][half*2+1]);
                    *(float2*)(Cp + nt * 8) = v;
                }
            }
        }
    }
}

// ---------------- host launcher ----------------
extern "C" void kernel_launch(void* const* d_in, const int* in_sizes, int n_in,
                              void* d_out, int out_size) {
    const float* x  = (const float*)d_in[0];
    const float* rw = (const float*)d_in[1];
    const float* w1 = (const float*)d_in[2];
    const float* w3 = (const float*)d_in[3];
    const float* w2 = (const float*)d_in[4];
    float* out = (float*)d_out;

    cudaFuncSetAttribute(gemm_fp16<0>, cudaFuncAttributeMaxDynamicSharedMemorySize, DYN_SMEM);
    cudaFuncSetAttribute(gemm_fp16<1>, cudaFuncAttributeMaxDynamicSharedMemorySize, DYN_SMEM);

    init_small_kernel<<<1, 32>>>();

    cvt_x_kernel<<<1024, 256>>>(x);
    cvt_w_kernel<0><<<4096, 256>>>(w1);
    cvt_w_kernel<1><<<4096, 256>>>(w3);
    cvt_w_kernel<2><<<4096, 256>>>(w2);

    router_kernel<<<TTOK / 8, 256>>>(x, rw);
    scan_kernel<<<1, 32>>>();
    scatter_kernel<<<NSLOT / 256, 256>>>();

    // gate+up fused launch: x = 16 (8 gate N-tiles + 8 up N-tiles)
    dim3 ggu(2 * (HD/BN), NSLOT/BM, NE);
    gemm_fp16<0><<<ggu, 512, DYN_SMEM>>>();

    swiglu_kernel<<<2048, 256>>>();

    dim3 gd(HD/BN, NSLOT/BM, NE);
    gemm_fp16<1><<<gd, 512, DYN_SMEM>>>();

    combine_kernel<<<(TTOK * HD / 4) / 256, 256>>>(out);
}

// round 5
// speedup vs baseline: 2.3182x; 1.0007x over previous
#include <cuda_runtime.h>
#include <cuda_fp16.h>
#include <cstdint>
#include <cstddef>

// Problem constants: T=4096, H=I=2048, E=8, top-2
#define TTOK 4096
#define HD   2048
#define NE   8
#define NSLOT (2*TTOK)

// GEMM tiling: CTA 128(M) x 256(N), K-chunk 32, 4-stage cp.async ring, 512 thr
#define BM 128
#define BN 256
#define BKC 32
#define NCHUNK (HD/BKC)     // 64
#define NSTG 4

// smem byte offsets within one stage
#define AA_B 0              // A: 128 rows x 40 halves = 10240 B (row stride 80B)
#define BB_B 10240          // B: 32 rows x 264 halves = 16896 B (row stride 528B)
#define STG_B 27136
#define DYN_SMEM (NSTG*STG_B)   // 108544 B

// ---------------- device scratch ----------------
__device__ int   g_counts[NE];
__device__ int   g_offs[NE+1];
__device__ int   g_cursor[NE];
__device__ int   g_top_idx[NSLOT];
__device__ float g_top_scale[NSLOT];
__device__ int   g_slot_tok[NSLOT];
__device__ int   g_tok_pos[NSLOT];

__device__ __align__(16) __half g_x16[(size_t)TTOK*HD];
__device__ __align__(16) __half g_w1[(size_t)NE*HD*HD];   // [e][k][n] fp16
__device__ __align__(16) __half g_w3[(size_t)NE*HD*HD];
__device__ __align__(16) __half g_w2[(size_t)NE*HD*HD];
__device__ __align__(16) float  g_gbuf[(size_t)NSLOT*HD];
__device__ __align__(16) float  g_ubuf[(size_t)NSLOT*HD];
__device__ __align__(16) __half g_act[(size_t)NSLOT*HD];

// ---------------- helpers ----------------
__device__ __forceinline__ uint32_t smem_u32(const void* p) {
    return (uint32_t)__cvta_generic_to_shared(p);
}
__device__ __forceinline__ void cp16(uint32_t dst, const void* src, int szbytes) {
    asm volatile("cp.async.cg.shared.global [%0], [%1], 16, %2;\n"
                 :: "r"(dst), "l"(src), "r"(szbytes));
}
__device__ __forceinline__ void cp_commit() {
    asm volatile("cp.async.commit_group;\n");
}
__device__ __forceinline__ void wait_n(int n) {
    if (n >= 2)      asm volatile("cp.async.wait_group 2;\n" ::: "memory");
    else if (n == 1) asm volatile("cp.async.wait_group 1;\n" ::: "memory");
    else             asm volatile("cp.async.wait_group 0;\n" ::: "memory");
}
__device__ __forceinline__ void ldsm_x4(uint32_t (&r)[4], uint32_t addr) {
    asm volatile("ldmatrix.sync.aligned.m8n8.x4.shared.b16 {%0,%1,%2,%3}, [%4];\n"
                 : "=r"(r[0]), "=r"(r[1]), "=r"(r[2]), "=r"(r[3]) : "r"(addr));
}
__device__ __forceinline__ void ldsm_x4_t(uint32_t (&r)[4], uint32_t addr) {
    asm volatile("ldmatrix.sync.aligned.m8n8.x4.trans.shared.b16 {%0,%1,%2,%3}, [%4];\n"
                 : "=r"(r[0]), "=r"(r[1]), "=r"(r[2]), "=r"(r[3]) : "r"(addr));
}
__device__ __forceinline__ void mma16816(float (&c)[4], const uint32_t (&a)[4],
                                         uint32_t b0, uint32_t b1) {
    asm volatile(
        "mma.sync.aligned.m16n8k16.row.col.f32.f16.f16.f32 "
        "{%0,%1,%2,%3}, {%4,%5,%6,%7}, {%8,%9}, {%0,%1,%2,%3};\n"
        : "+f"(c[0]), "+f"(c[1]), "+f"(c[2]), "+f"(c[3])
        : "r"(a[0]), "r"(a[1]), "r"(a[2]), "r"(a[3]), "r"(b0), "r"(b1));
}

// ---------------- setup kernels ----------------
__global__ void init_small_kernel() {
    int i = threadIdx.x;
    if (i < NE) { g_counts[i] = 0; g_cursor[i] = 0; }
}

// x: fp32 -> fp16
__global__ void cvt_x_kernel(const float* __restrict__ src) {
    size_t n4 = ((size_t)TTOK * HD) >> 2;
    const float4* s4 = (const float4*)src;
    __half2* d2 = (__half2*)g_x16;
    size_t stride = (size_t)gridDim.x * blockDim.x;
    for (size_t i = (size_t)blockIdx.x * blockDim.x + threadIdx.x; i < n4; i += stride) {
        float4 v = s4[i];
        d2[2*i]   = __floats2half2_rn(v.x, v.y);
        d2[2*i+1] = __floats2half2_rn(v.z, v.w);
    }
}

// weights: fp32 -> fp16 (layout unchanged [e][k][n])
template <int W>
__global__ void cvt_w_kernel(const float* __restrict__ src) {
    __half* d = (W == 0) ? g_w1 : (W == 1) ? g_w3 : g_w2;
    size_t n4 = ((size_t)NE * HD * HD) >> 2;
    const float4* s4 = (const float4*)src;
    __half2* d2 = (__half2*)d;
    size_t stride = (size_t)gridDim.x * blockDim.x;
    for (size_t i = (size_t)blockIdx.x * blockDim.x + threadIdx.x; i < n4; i += stride) {
        float4 v = s4[i];
        d2[2*i]   = __floats2half2_rn(v.x, v.y);
        d2[2*i+1] = __floats2half2_rn(v.z, v.w);
    }
}

// Router: one warp per token
__global__ void router_kernel(const float* __restrict__ x,
                              const float* __restrict__ rw) {
    int warp = threadIdx.x >> 5;
    int t = blockIdx.x * (blockDim.x >> 5) + warp;
    if (t >= TTOK) return;
    int lane = threadIdx.x & 31;
    float acc[NE];
#pragma unroll
    for (int e = 0; e < NE; e++) acc[e] = 0.f;
    const float* xr = x + (size_t)t * HD;
    for (int h = lane; h < HD; h += 32) {
        float xv = xr[h];
        const float* r = rw + (size_t)h * NE;
#pragma unroll
        for (int e = 0; e < NE; e++) acc[e] = fmaf(xv, r[e], acc[e]);
    }
#pragma unroll
    for (int e = 0; e < NE; e++) {
#pragma unroll
        for (int o = 16; o; o >>= 1) acc[e] += __shfl_xor_sync(0xffffffffu, acc[e], o);
    }
    if (lane == 0) {
        int i0 = 0; float v0 = acc[0];
#pragma unroll
        for (int e = 1; e < NE; e++) if (acc[e] > v0) { v0 = acc[e]; i0 = e; }
        int i1 = -1; float v1 = -3.4e38f;
#pragma unroll
        for (int e = 0; e < NE; e++) if (e != i0 && acc[e] > v1) { v1 = acc[e]; i1 = e; }
        float ex = expf(v1 - v0);
        float inv = 1.f / (1.f + ex);
        g_top_idx[2*t]   = i0; g_top_scale[2*t]   = inv;
        g_top_idx[2*t+1] = i1; g_top_scale[2*t+1] = ex * inv;
        atomicAdd(&g_counts[i0], 1);
        atomicAdd(&g_counts[i1], 1);
    }
}

__global__ void scan_kernel() {
    if (threadIdx.x == 0) {
        int o = 0;
        for (int e = 0; e < NE; e++) { g_offs[e] = o; g_cursor[e] = o; o += g_counts[e]; }
        g_offs[NE] = o;
    }
}

__global__ void scatter_kernel() {
    int i = blockIdx.x * blockDim.x + threadIdx.x;
    if (i < NSLOT) {
        int e = g_top_idx[i];
        int pos = atomicAdd(&g_cursor[e], 1);
        g_slot_tok[pos] = i >> 1;
        g_tok_pos[i] = pos;
    }
}

// swiglu -> fp16 activation
__global__ void swiglu_kernel() {
    size_t n4 = ((size_t)NSLOT * HD) >> 2;
    const float4* g4 = (const float4*)g_gbuf;
    const float4* u4 = (const float4*)g_ubuf;
    __half2* a2 = (__half2*)g_act;
    size_t stride = (size_t)gridDim.x * blockDim.x;
    for (size_t i = (size_t)blockIdx.x * blockDim.x + threadIdx.x; i < n4; i += stride) {
        float4 g = g4[i], u = u4[i];
        float a0 = u.x * (g.x / (1.f + __expf(-g.x)));
        float a1 = u.y * (g.y / (1.f + __expf(-g.y)));
        float a2v = u.z * (g.z / (1.f + __expf(-g.z)));
        float a3 = u.w * (g.w / (1.f + __expf(-g.w)));
        a2[2*i]   = __floats2half2_rn(a0, a1);
        a2[2*i+1] = __floats2half2_rn(a2v, a3);
    }
}

// combine: out[t] = s0*down[pos0] + s1*down[pos1]
__global__ void combine_kernel(float* __restrict__ out) {
    int i = blockIdx.x * blockDim.x + threadIdx.x;
    int t  = i >> 9;           // HD/4 = 512 float4 per token
    int h4 = i & 511;
    float s0 = g_top_scale[2*t], s1 = g_top_scale[2*t+1];
    int p0 = g_tok_pos[2*t], p1 = g_tok_pos[2*t+1];
    float4 a = ((const float4*)(g_gbuf + (size_t)p0 * HD))[h4];
    float4 b = ((const float4*)(g_gbuf + (size_t)p1 * HD))[h4];
    float4 o;
    o.x = s0*a.x + s1*b.x; o.y = s0*a.y + s1*b.y;
    o.z = s0*a.z + s1*b.z; o.w = s0*a.w + s1*b.w;
    ((float4*)(out + (size_t)t * HD))[h4] = o;
}

// ---------------- grouped gather-GEMM, pure fp16, f32 accumulate ----------------
// MODE 0: gate+up  (A = gathered x; blockIdx.x < 8 -> w1/gbuf, >= 8 -> w3/ubuf)
// MODE 1: down     (A = act slots; B = w2; C = gbuf)
template <int MODE>
__global__ void __launch_bounds__(512, 1)
gemm_fp16() {
    extern __shared__ __align__(128) char sm[];
    const int e = blockIdx.z;
    const int rowBeg = g_offs[e], rowEnd = g_offs[e+1];
    const int row0 = rowBeg + blockIdx.y * BM;
    if (row0 >= rowEnd) return;

    const int xb = blockIdx.x;
    const __half *Aw, *Bw;
    float* Cb;
    int n0;
    if (MODE == 0) {
        bool up = xb >= (HD/BN);
        n0 = (xb & (HD/BN - 1)) * BN;
        Aw = g_x16;
        Bw = (up ? g_w3 : g_w1) + (size_t)e * HD * HD;
        Cb = up ? g_ubuf : g_gbuf;
    } else {
        n0 = xb * BN;
        Aw = g_act;
        Bw = g_w2 + (size_t)e * HD * HD;
        Cb = g_gbuf;
    }

    const int tid = threadIdx.x;
    const uint32_t sb = smem_u32(sm);

    // ---- load mappings ----
    // A: 512 threads -> 128 rows x 4 x 16B segments
    const int arow = tid >> 2, aseg = tid & 3;
    const int aslot = row0 + arow;
    const bool av = aslot < rowEnd;
    const int tok = av ? ((MODE == 0) ? g_slot_tok[aslot] : aslot) : 0;
    const __half* aSrc = Aw + (size_t)tok * HD + aseg * 8;
    const int asz = av ? 16 : 0;
    const uint32_t aDst = (uint32_t)(arow * 80 + aseg * 16);
    // B: 2 x (512 threads) -> 32 k-rows x 32 x 16B segments
    const int bk = tid >> 5, bseg = tid & 31;
    const __half* bSrc = Bw + (size_t)bk * HD + n0 + bseg * 8;
    const uint32_t bDst = (uint32_t)(bk * 528 + bseg * 16);

    auto load_stage = [&](int c, int stg) {
        uint32_t st = sb + (uint32_t)stg * STG_B;
        size_t k0 = (size_t)c * BKC;
        cp16(st + AA_B + aDst, aSrc + k0, asz);
        const __half* bp = bSrc + k0 * HD;
        cp16(st + BB_B + bDst, bp, 16);
        cp16(st + BB_B + bDst + 16 * 528, bp + (size_t)16 * HD, 16);
        cp_commit();
    };

    const int wid = tid >> 5, lane = tid & 31;
    const int wm = wid & 3, wn = wid >> 2;        // 4 warps M x 4 warps N, warp tile 32x64
    const int ar = lane & 15, ac = (lane >> 4) * 8;
    const int br = lane & 15, bc = (lane >> 4) * 8;

    float acc[2][8][4];
#pragma unroll
    for (int mt = 0; mt < 2; mt++)
#pragma unroll
        for (int nt = 0; nt < 8; nt++)
#pragma unroll
            for (int q = 0; q < 4; q++) acc[mt][nt][q] = 0.f;

    load_stage(0, 0);
    load_stage(1, 1);
    load_stage(2, 2);

    for (int c = 0; c < NCHUNK; c++) {
        int rem = NCHUNK - 1 - c;
        wait_n(rem >= 2 ? 2 : rem);
        __syncthreads();
        if (c + 3 < NCHUNK) load_stage(c + 3, (c + 3) & 3);
        uint32_t stb = sb + (uint32_t)(c & 3) * STG_B;

#pragma unroll
        for (int kk = 0; kk < 2; kk++) {
            uint32_t a[2][4];
#pragma unroll
            for (int mt = 0; mt < 2; mt++) {
                uint32_t aaddr = stb + AA_B
                    + (uint32_t)((wm * 32 + mt * 16 + ar) * 80 + (kk * 16 + ac) * 2);
                ldsm_x4(a[mt], aaddr);
            }
#pragma unroll
            for (int p = 0; p < 4; p++) {
                uint32_t b[4];
                uint32_t baddr = stb + BB_B
                    + (uint32_t)((kk * 16 + br) * 528 + (wn * 64 + p * 16 + bc) * 2);
                ldsm_x4_t(b, baddr);
                mma16816(acc[0][2*p],   a[0], b[0], b[1]);
                mma16816(acc[0][2*p+1], a[0], b[2], b[3]);
                mma16816(acc[1][2*p],   a[1], b[0], b[1]);
                mma16816(acc[1][2*p+1], a[1], b[2], b[3]);
            }
        }
    }

    // ---- epilogue ----
    const int rIn = lane >> 2, cIn = (lane & 3) * 2;
#pragma unroll
    for (int mt = 0; mt < 2; mt++) {
#pragma unroll
        for (int half = 0; half < 2; half++) {
            int slot = row0 + wm * 32 + mt * 16 + rIn + half * 8;
            if (slot < rowEnd) {
                float* Cp = Cb + (size_t)slot * HD + n0 + wn * 64 + cIn;
#pragma unroll
                for (int nt = 0; nt < 8; nt++) {
                    float2 v = make_float2(acc[mt][nt][half*2], acc[mt][nt][half*2+1]);
                    *(float2*)(Cp + nt * 8) = v;
                }
            }
        }
    }
}

// ---------------- host launcher ----------------
extern "C" void kernel_launch(void* const* d_in, const int* in_sizes, int n_in,
                              void* d_out, int out_size) {
    const float* x  = (const float*)d_in[0];
    const float* rw = (const float*)d_in[1];
    const float* w1 = (const float*)d_in[2];
    const float* w3 = (const float*)d_in[3];
    const float* w2 = (const float*)d_in[4];
    float* out = (float*)d_out;

    cudaFuncSetAttribute(gemm_fp16<0>, cudaFuncAttributeMaxDynamicSharedMemorySize, DYN_SMEM);
    cudaFuncSetAttribute(gemm_fp16<1>, cudaFuncAttributeMaxDynamicSharedMemorySize, DYN_SMEM);

    init_small_kernel<<<1, 32>>>();

    cvt_x_kernel<<<1024, 256>>>(x);
    cvt_w_kernel<0><<<4096, 256>>>(w1);
    cvt_w_kernel<1><<<4096, 256>>>(w3);
    cvt_w_kernel<2><<<4096, 256>>>(w2);

    router_kernel<<<TTOK / 8, 256>>>(x, rw);
    scan_kernel<<<1, 32>>>();
    scatter_kernel<<<NSLOT / 256, 256>>>();

    // gate+up fused launch: x = 16 (8 gate N-tiles + 8 up N-tiles)
    dim3 ggu(2 * (HD/BN), NSLOT/BM, NE);
    gemm_fp16<0><<<ggu, 512, DYN_SMEM>>>();

    swiglu_kernel<<<2048, 256>>>();

    dim3 gd(HD/BN, NSLOT/BM, NE);
    gemm_fp16<1><<<gd, 512, DYN_SMEM>>>();

    combine_kernel<<<(TTOK * HD / 4) / 256, 256>>>(out);
}

// round 6
// speedup vs baseline: 2.5530x; 1.1013x over previous
#include <cuda_runtime.h>
#include <cuda_fp16.h>
#include <cstdint>
#include <cstddef>

// Problem constants: T=4096, H=I=2048, E=8, top-2
#define TTOK 4096
#define HD   2048
#define NE   8
#define NSLOT (2*TTOK)

// GEMM tiling: CTA 128(M) x 256(N), K-chunk 64, 3-stage cp.async ring, 512 thr
#define BM 128
#define BN 256
#define BKC 64
#define NCHUNK (HD/BKC)     // 32
#define NSTG 3

// smem byte offsets within one stage
#define AA_B 0              // A: 128 rows x 72 halves (144B stride) = 18432 B
#define BB_B 18432          // B: 64 rows x 264 halves (528B stride) = 33792 B
#define STG_B 52224
#define DYN_SMEM (NSTG*STG_B)   // 156672 B

// ---------------- device scratch ----------------
__device__ int   g_counts[NE];
__device__ int   g_offs[NE+1];
__device__ int   g_cursor[NE];
__device__ int   g_top_idx[NSLOT];
__device__ float g_top_scale[NSLOT];
__device__ int   g_slot_tok[NSLOT];
__device__ int   g_tok_pos[NSLOT];

__device__ __align__(16) __half g_x16[(size_t)TTOK*HD];
__device__ __align__(16) __half g_w1[(size_t)NE*HD*HD];   // [e][k][n] fp16
__device__ __align__(16) __half g_w3[(size_t)NE*HD*HD];
__device__ __align__(16) __half g_w2[(size_t)NE*HD*HD];
__device__ __align__(16) __half g_g16[(size_t)NSLOT*HD];  // gate (fp16)
__device__ __align__(16) __half g_u16[(size_t)NSLOT*HD];  // up   (fp16)
__device__ __align__(16) __half g_act[(size_t)NSLOT*HD];  // swiglu out (fp16)
__device__ __align__(16) float  g_gbuf[(size_t)NSLOT*HD]; // down out (fp32)

// ---------------- helpers ----------------
__device__ __forceinline__ uint32_t smem_u32(const void* p) {
    return (uint32_t)__cvta_generic_to_shared(p);
}
__device__ __forceinline__ void cp16(uint32_t dst, const void* src, int szbytes) {
    asm volatile("cp.async.cg.shared.global [%0], [%1], 16, %2;\n"
                 :: "r"(dst), "l"(src), "r"(szbytes));
}
__device__ __forceinline__ void cp_commit() {
    asm volatile("cp.async.commit_group;\n");
}
__device__ __forceinline__ void ldsm_x4(uint32_t (&r)[4], uint32_t addr) {
    asm volatile("ldmatrix.sync.aligned.m8n8.x4.shared.b16 {%0,%1,%2,%3}, [%4];\n"
                 : "=r"(r[0]), "=r"(r[1]), "=r"(r[2]), "=r"(r[3]) : "r"(addr));
}
__device__ __forceinline__ void ldsm_x4_t(uint32_t (&r)[4], uint32_t addr) {
    asm volatile("ldmatrix.sync.aligned.m8n8.x4.trans.shared.b16 {%0,%1,%2,%3}, [%4];\n"
                 : "=r"(r[0]), "=r"(r[1]), "=r"(r[2]), "=r"(r[3]) : "r"(addr));
}
__device__ __forceinline__ void mma16816(float (&c)[4], const uint32_t (&a)[4],
                                         uint32_t b0, uint32_t b1) {
    asm volatile(
        "mma.sync.aligned.m16n8k16.row.col.f32.f16.f16.f32 "
        "{%0,%1,%2,%3}, {%4,%5,%6,%7}, {%8,%9}, {%0,%1,%2,%3};\n"
        : "+f"(c[0]), "+f"(c[1]), "+f"(c[2]), "+f"(c[3])
        : "r"(a[0]), "r"(a[1]), "r"(a[2]), "r"(a[3]), "r"(b0), "r"(b1));
}

// ---------------- setup kernels ----------------
__global__ void init_small_kernel() {
    int i = threadIdx.x;
    if (i < NE) { g_counts[i] = 0; g_cursor[i] = 0; }
}

// x: fp32 -> fp16
__global__ void cvt_x_kernel(const float* __restrict__ src) {
    size_t n4 = ((size_t)TTOK * HD) >> 2;
    const float4* s4 = (const float4*)src;
    __half2* d2 = (__half2*)g_x16;
    size_t stride = (size_t)gridDim.x * blockDim.x;
    for (size_t i = (size_t)blockIdx.x * blockDim.x + threadIdx.x; i < n4; i += stride) {
        float4 v = s4[i];
        d2[2*i]   = __floats2half2_rn(v.x, v.y);
        d2[2*i+1] = __floats2half2_rn(v.z, v.w);
    }
}

// weights: fp32 -> fp16 (layout unchanged [e][k][n])
template <int W>
__global__ void cvt_w_kernel(const float* __restrict__ src) {
    __half* d = (W == 0) ? g_w1 : (W == 1) ? g_w3 : g_w2;
    size_t n4 = ((size_t)NE * HD * HD) >> 2;
    const float4* s4 = (const float4*)src;
    __half2* d2 = (__half2*)d;
    size_t stride = (size_t)gridDim.x * blockDim.x;
    for (size_t i = (size_t)blockIdx.x * blockDim.x + threadIdx.x; i < n4; i += stride) {
        float4 v = s4[i];
        d2[2*i]   = __floats2half2_rn(v.x, v.y);
        d2[2*i+1] = __floats2half2_rn(v.z, v.w);
    }
}

// Router: one warp per token
__global__ void router_kernel(const float* __restrict__ x,
                              const float* __restrict__ rw) {
    int warp = threadIdx.x >> 5;
    int t = blockIdx.x * (blockDim.x >> 5) + warp;
    if (t >= TTOK) return;
    int lane = threadIdx.x & 31;
    float acc[NE];
#pragma unroll
    for (int e = 0; e < NE; e++) acc[e] = 0.f;
    const float* xr = x + (size_t)t * HD;
    for (int h = lane; h < HD; h += 32) {
        float xv = xr[h];
        const float* r = rw + (size_t)h * NE;
#pragma unroll
        for (int e = 0; e < NE; e++) acc[e] = fmaf(xv, r[e], acc[e]);
    }
#pragma unroll
    for (int e = 0; e < NE; e++) {
#pragma unroll
        for (int o = 16; o; o >>= 1) acc[e] += __shfl_xor_sync(0xffffffffu, acc[e], o);
    }
    if (lane == 0) {
        int i0 = 0; float v0 = acc[0];
#pragma unroll
        for (int e = 1; e < NE; e++) if (acc[e] > v0) { v0 = acc[e]; i0 = e; }
        int i1 = -1; float v1 = -3.4e38f;
#pragma unroll
        for (int e = 0; e < NE; e++) if (e != i0 && acc[e] > v1) { v1 = acc[e]; i1 = e; }
        float ex = expf(v1 - v0);
        float inv = 1.f / (1.f + ex);
        g_top_idx[2*t]   = i0; g_top_scale[2*t]   = inv;
        g_top_idx[2*t+1] = i1; g_top_scale[2*t+1] = ex * inv;
        atomicAdd(&g_counts[i0], 1);
        atomicAdd(&g_counts[i1], 1);
    }
}

__global__ void scan_kernel() {
    if (threadIdx.x == 0) {
        int o = 0;
        for (int e = 0; e < NE; e++) { g_offs[e] = o; g_cursor[e] = o; o += g_counts[e]; }
        g_offs[NE] = o;
    }
}

__global__ void scatter_kernel() {
    int i = blockIdx.x * blockDim.x + threadIdx.x;
    if (i < NSLOT) {
        int e = g_top_idx[i];
        int pos = atomicAdd(&g_cursor[e], 1);
        g_slot_tok[pos] = i >> 1;
        g_tok_pos[i] = pos;
    }
}

// swiglu (fp16 in, fp16 out)
__global__ void swiglu_kernel() {
    size_t n2 = ((size_t)NSLOT * HD) >> 1;
    const __half2* g2 = (const __half2*)g_g16;
    const __half2* u2 = (const __half2*)g_u16;
    __half2* a2 = (__half2*)g_act;
    size_t stride = (size_t)gridDim.x * blockDim.x;
    for (size_t i = (size_t)blockIdx.x * blockDim.x + threadIdx.x; i < n2; i += stride) {
        float2 g = __half22float2(g2[i]);
        float2 u = __half22float2(u2[i]);
        float a0 = u.x * (g.x / (1.f + __expf(-g.x)));
        float a1 = u.y * (g.y / (1.f + __expf(-g.y)));
        a2[i] = __floats2half2_rn(a0, a1);
    }
}

// combine: out[t] = s0*down[pos0] + s1*down[pos1]
__global__ void combine_kernel(float* __restrict__ out) {
    int i = blockIdx.x * blockDim.x + threadIdx.x;
    int t  = i >> 9;           // HD/4 = 512 float4 per token
    int h4 = i & 511;
    float s0 = g_top_scale[2*t], s1 = g_top_scale[2*t+1];
    int p0 = g_tok_pos[2*t], p1 = g_tok_pos[2*t+1];
    float4 a = ((const float4*)(g_gbuf + (size_t)p0 * HD))[h4];
    float4 b = ((const float4*)(g_gbuf + (size_t)p1 * HD))[h4];
    float4 o;
    o.x = s0*a.x + s1*b.x; o.y = s0*a.y + s1*b.y;
    o.z = s0*a.z + s1*b.z; o.w = s0*a.w + s1*b.w;
    ((float4*)(out + (size_t)t * HD))[h4] = o;
}

// ---------------- grouped gather-GEMM, fp16, f32 accumulate ----------------
// MODE 0: gate+up  (A = gathered x; blockIdx.x < 8 -> w1/g16, >= 8 -> w3/u16)
// MODE 1: down     (A = act slots; B = w2; C = gbuf fp32)
template <int MODE>
__global__ void __launch_bounds__(512, 1)
gemm_fp16() {
    extern __shared__ __align__(128) char sm[];
    const int e = blockIdx.z;
    const int rowBeg = g_offs[e], rowEnd = g_offs[e+1];
    const int row0 = rowBeg + blockIdx.y * BM;
    if (row0 >= rowEnd) return;

    const int xb = blockIdx.x;
    const __half *Aw, *Bw;
    __half* C16 = nullptr;
    float* C32 = nullptr;
    int n0;
    if (MODE == 0) {
        bool up = xb >= (HD/BN);
        n0 = (xb & (HD/BN - 1)) * BN;
        Aw = g_x16;
        Bw = (up ? g_w3 : g_w1) + (size_t)e * HD * HD;
        C16 = up ? g_u16 : g_g16;
    } else {
        n0 = xb * BN;
        Aw = g_act;
        Bw = g_w2 + (size_t)e * HD * HD;
        C32 = g_gbuf;
    }

    const int tid = threadIdx.x;
    const uint32_t sb = smem_u32(sm);

    // ---- load mappings ----
    // A: 1024 cp16 per stage (128 rows x 8 segs); 512 thr -> 2 each
    const int ar0 = tid >> 2;                 // rows tid/4 and tid/4+? -> use idx scheme
    // idx = i*512 + tid; row = idx>>3, seg = idx&7
    const __half* aSrc[2]; int aSz[2]; uint32_t aDst[2];
#pragma unroll
    for (int i = 0; i < 2; i++) {
        int idx = i * 512 + tid, row = idx >> 3, seg = idx & 7;
        int aslot = row0 + row;
        bool av = aslot < rowEnd;
        int tok = av ? ((MODE == 0) ? g_slot_tok[aslot] : aslot) : 0;
        aSrc[i] = Aw + (size_t)tok * HD + seg * 8;
        aSz[i] = av ? 16 : 0;
        aDst[i] = (uint32_t)(row * 144 + seg * 16);
    }
    // B: 2048 cp16 per stage (64 rows x 32 segs); 512 thr -> 4 each
    const __half* bSrc[4]; uint32_t bDst[4];
#pragma unroll
    for (int i = 0; i < 4; i++) {
        int idx = i * 512 + tid, row = idx >> 5, seg = idx & 31;
        bSrc[i] = Bw + (size_t)row * HD + n0 + seg * 8;
        bDst[i] = (uint32_t)(row * 528 + seg * 16);
    }

    auto load_stage = [&](int c, int stg) {
        uint32_t st = sb + (uint32_t)stg * STG_B;
        size_t k0 = (size_t)c * BKC;
#pragma unroll
        for (int i = 0; i < 2; i++) cp16(st + AA_B + aDst[i], aSrc[i] + k0, aSz[i]);
#pragma unroll
        for (int i = 0; i < 4; i++) cp16(st + BB_B + bDst[i], bSrc[i] + k0 * HD, 16);
        cp_commit();
    };

    const int wid = tid >> 5, lane = tid & 31;
    const int wm = wid & 3, wn = wid >> 2;        // 4 warps M x 4 warps N, warp tile 32x64
    const int ar = lane & 15, ac = (lane >> 4) * 8;
    const int br = lane & 15, bc = (lane >> 4) * 8;

    float acc[2][8][4];
#pragma unroll
    for (int mt = 0; mt < 2; mt++)
#pragma unroll
        for (int nt = 0; nt < 8; nt++)
#pragma unroll
            for (int q = 0; q < 4; q++) acc[mt][nt][q] = 0.f;

    load_stage(0, 0);
    load_stage(1, 1);

    for (int c = 0; c < NCHUNK; c++) {
        if (c + 1 < NCHUNK) asm volatile("cp.async.wait_group 1;\n" ::: "memory");
        else                asm volatile("cp.async.wait_group 0;\n" ::: "memory");
        __syncthreads();
        if (c + 2 < NCHUNK) load_stage(c + 2, (c + 2) % NSTG);
        uint32_t stb = sb + (uint32_t)(c % NSTG) * STG_B;

#pragma unroll
        for (int kk = 0; kk < 4; kk++) {
            uint32_t a[2][4];
#pragma unroll
            for (int mt = 0; mt < 2; mt++) {
                uint32_t aaddr = stb + AA_B
                    + (uint32_t)((wm * 32 + mt * 16 + ar) * 144 + (kk * 16 + ac) * 2);
                ldsm_x4(a[mt], aaddr);
            }
#pragma unroll
            for (int p = 0; p < 4; p++) {
                uint32_t b[4];
                uint32_t baddr = stb + BB_B
                    + (uint32_t)((kk * 16 + br) * 528 + (wn * 64 + p * 16 + bc) * 2);
                ldsm_x4_t(b, baddr);
                mma16816(acc[0][2*p],   a[0], b[0], b[1]);
                mma16816(acc[0][2*p+1], a[0], b[2], b[3]);
                mma16816(acc[1][2*p],   a[1], b[0], b[1]);
                mma16816(acc[1][2*p+1], a[1], b[2], b[3]);
            }
        }
    }

    // ---- epilogue ----
    const int rIn = lane >> 2, cIn = (lane & 3) * 2;
#pragma unroll
    for (int mt = 0; mt < 2; mt++) {
#pragma unroll
        for (int half = 0; half < 2; half++) {
            int slot = row0 + wm * 32 + mt * 16 + rIn + half * 8;
            if (slot < rowEnd) {
                if (MODE == 0) {
                    __half* Cp = C16 + (size_t)slot * HD + n0 + wn * 64 + cIn;
#pragma unroll
                    for (int nt = 0; nt < 8; nt++) {
                        *(__half2*)(Cp + nt * 8) =
                            __floats2half2_rn(acc[mt][nt][half*2], acc[mt][nt][half*2+1]);
                    }
                } else {
                    float* Cp = C32 + (size_t)slot * HD + n0 + wn * 64 + cIn;
#pragma unroll
                    for (int nt = 0; nt < 8; nt++) {
                        float2 v = make_float2(acc[mt][nt][half*2], acc[mt][nt][half*2+1]);
                        *(float2*)(Cp + nt * 8) = v;
                    }
                }
            }
        }
    }
}

// ---------------- host launcher ----------------
extern "C" void kernel_launch(void* const* d_in, const int* in_sizes, int n_in,
                              void* d_out, int out_size) {
    const float* x  = (const float*)d_in[0];
    const float* rw = (const float*)d_in[1];
    const float* w1 = (const float*)d_in[2];
    const float* w3 = (const float*)d_in[3];
    const float* w2 = (const float*)d_in[4];
    float* out = (float*)d_out;

    cudaFuncSetAttribute(gemm_fp16<0>, cudaFuncAttributeMaxDynamicSharedMemorySize, DYN_SMEM);
    cudaFuncSetAttribute(gemm_fp16<1>, cudaFuncAttributeMaxDynamicSharedMemorySize, DYN_SMEM);

    init_small_kernel<<<1, 32>>>();

    cvt_x_kernel<<<1024, 256>>>(x);
    cvt_w_kernel<0><<<4096, 256>>>(w1);
    cvt_w_kernel<1><<<4096, 256>>>(w3);
    cvt_w_kernel<2><<<4096, 256>>>(w2);

    router_kernel<<<TTOK / 8, 256>>>(x, rw);
    scan_kernel<<<1, 32>>>();
    scatter_kernel<<<NSLOT / 256, 256>>>();

    // gate+up fused launch: x = 16 (8 gate N-tiles + 8 up N-tiles)
    dim3 ggu(2 * (HD/BN), NSLOT/BM, NE);
    gemm_fp16<0><<<ggu, 512, DYN_SMEM>>>();

    swiglu_kernel<<<2048, 256>>>();

    dim3 gd(HD/BN, NSLOT/BM, NE);
    gemm_fp16<1><<<gd, 512, DYN_SMEM>>>();

    combine_kernel<<<(TTOK * HD / 4) / 256, 256>>>(out);
}

// round 7
// speedup vs baseline: 2.6037x; 1.0198x over previous
#include <cuda_runtime.h>
#include <cuda_fp16.h>
#include <cstdint>
#include <cstddef>

// Problem constants: T=4096, H=I=2048, E=8, top-2
#define TTOK 4096
#define HD   2048
#define NE   8
#define NSLOT (2*TTOK)

#define BM 128
#define BKC 64
#define NCHUNK (HD/BKC)     // 32
#define NSTG 3

// ---- fused gate+up GEMM tile: 128(M) x 128(N), dual-B ----
#define GU_BN 128
#define GU_AA 0                 // A: 128 rows x 144B stride = 18432
#define GU_B1 18432             // B1: 64 rows x 272B stride = 17408
#define GU_B2 35840             // B2: 17408
#define GU_STG 53248
#define GU_SMEM (NSTG*GU_STG)   // 159744

// ---- down GEMM tile: 128(M) x 256(N) ----
#define DN_BN 256
#define DN_AA 0                 // A: 128 rows x 144B stride = 18432
#define DN_BB 18432             // B: 64 rows x 528B stride = 33792
#define DN_STG 52224
#define DN_SMEM (NSTG*DN_STG)   // 156672

// ---------------- device scratch ----------------
__device__ int   g_counts[NE];
__device__ int   g_offs[NE+1];
__device__ int   g_cursor[NE];
__device__ int   g_top_idx[NSLOT];
__device__ float g_top_scale[NSLOT];
__device__ int   g_slot_tok[NSLOT];
__device__ int   g_tok_pos[NSLOT];

__device__ __align__(16) __half g_x16[(size_t)TTOK*HD];
__device__ __align__(16) __half g_w1[(size_t)NE*HD*HD];   // [e][k][n] fp16
__device__ __align__(16) __half g_w3[(size_t)NE*HD*HD];
__device__ __align__(16) __half g_w2[(size_t)NE*HD*HD];
__device__ __align__(16) __half g_act[(size_t)NSLOT*HD];  // silu(gate)*up (fp16)
__device__ __align__(16) float  g_gbuf[(size_t)NSLOT*HD]; // down out (fp32)

// ---------------- helpers ----------------
__device__ __forceinline__ uint32_t smem_u32(const void* p) {
    return (uint32_t)__cvta_generic_to_shared(p);
}
__device__ __forceinline__ void cp16(uint32_t dst, const void* src, int szbytes) {
    asm volatile("cp.async.cg.shared.global [%0], [%1], 16, %2;\n"
                 :: "r"(dst), "l"(src), "r"(szbytes));
}
__device__ __forceinline__ void cp_commit() {
    asm volatile("cp.async.commit_group;\n");
}
__device__ __forceinline__ void ldsm_x4(uint32_t (&r)[4], uint32_t addr) {
    asm volatile("ldmatrix.sync.aligned.m8n8.x4.shared.b16 {%0,%1,%2,%3}, [%4];\n"
                 : "=r"(r[0]), "=r"(r[1]), "=r"(r[2]), "=r"(r[3]) : "r"(addr));
}
__device__ __forceinline__ void ldsm_x4_t(uint32_t (&r)[4], uint32_t addr) {
    asm volatile("ldmatrix.sync.aligned.m8n8.x4.trans.shared.b16 {%0,%1,%2,%3}, [%4];\n"
                 : "=r"(r[0]), "=r"(r[1]), "=r"(r[2]), "=r"(r[3]) : "r"(addr));
}
__device__ __forceinline__ void mma16816(float (&c)[4], const uint32_t (&a)[4],
                                         uint32_t b0, uint32_t b1) {
    asm volatile(
        "mma.sync.aligned.m16n8k16.row.col.f32.f16.f16.f32 "
        "{%0,%1,%2,%3}, {%4,%5,%6,%7}, {%8,%9}, {%0,%1,%2,%3};\n"
        : "+f"(c[0]), "+f"(c[1]), "+f"(c[2]), "+f"(c[3])
        : "r"(a[0]), "r"(a[1]), "r"(a[2]), "r"(a[3]), "r"(b0), "r"(b1));
}
__device__ __forceinline__ float silu_mul(float g, float u) {
    return u * (g / (1.f + __expf(-g)));
}

// ---------------- setup kernels ----------------
__global__ void init_small_kernel() {
    int i = threadIdx.x;
    if (i < NE) { g_counts[i] = 0; g_cursor[i] = 0; }
}

// x: fp32 -> fp16
__global__ void cvt_x_kernel(const float* __restrict__ src) {
    size_t n4 = ((size_t)TTOK * HD) >> 2;
    const float4* s4 = (const float4*)src;
    __half2* d2 = (__half2*)g_x16;
    size_t stride = (size_t)gridDim.x * blockDim.x;
    for (size_t i = (size_t)blockIdx.x * blockDim.x + threadIdx.x; i < n4; i += stride) {
        float4 v = s4[i];
        d2[2*i]   = __floats2half2_rn(v.x, v.y);
        d2[2*i+1] = __floats2half2_rn(v.z, v.w);
    }
}

// all three weights in one launch: blockIdx.y selects tensor
__global__ void cvt_w_all(const float* __restrict__ s1,
                          const float* __restrict__ s3,
                          const float* __restrict__ s2) {
    int which = blockIdx.y;
    const float* src = (which == 0) ? s1 : (which == 1) ? s3 : s2;
    __half* d = (which == 0) ? g_w1 : (which == 1) ? g_w3 : g_w2;
    size_t n4 = ((size_t)NE * HD * HD) >> 2;
    const float4* s4 = (const float4*)src;
    __half2* d2 = (__half2*)d;
    size_t stride = (size_t)gridDim.x * blockDim.x;
    for (size_t i = (size_t)blockIdx.x * blockDim.x + threadIdx.x; i < n4; i += stride) {
        float4 v = s4[i];
        d2[2*i]   = __floats2half2_rn(v.x, v.y);
        d2[2*i+1] = __floats2half2_rn(v.z, v.w);
    }
}

// Router: one warp per token
__global__ void router_kernel(const float* __restrict__ x,
                              const float* __restrict__ rw) {
    int warp = threadIdx.x >> 5;
    int t = blockIdx.x * (blockDim.x >> 5) + warp;
    if (t >= TTOK) return;
    int lane = threadIdx.x & 31;
    float acc[NE];
#pragma unroll
    for (int e = 0; e < NE; e++) acc[e] = 0.f;
    const float* xr = x + (size_t)t * HD;
    for (int h = lane; h < HD; h += 32) {
        float xv = xr[h];
        const float* r = rw + (size_t)h * NE;
#pragma unroll
        for (int e = 0; e < NE; e++) acc[e] = fmaf(xv, r[e], acc[e]);
    }
#pragma unroll
    for (int e = 0; e < NE; e++) {
#pragma unroll
        for (int o = 16; o; o >>= 1) acc[e] += __shfl_xor_sync(0xffffffffu, acc[e], o);
    }
    if (lane == 0) {
        int i0 = 0; float v0 = acc[0];
#pragma unroll
        for (int e = 1; e < NE; e++) if (acc[e] > v0) { v0 = acc[e]; i0 = e; }
        int i1 = -1; float v1 = -3.4e38f;
#pragma unroll
        for (int e = 0; e < NE; e++) if (e != i0 && acc[e] > v1) { v1 = acc[e]; i1 = e; }
        float ex = expf(v1 - v0);
        float inv = 1.f / (1.f + ex);
        g_top_idx[2*t]   = i0; g_top_scale[2*t]   = inv;
        g_top_idx[2*t+1] = i1; g_top_scale[2*t+1] = ex * inv;
        atomicAdd(&g_counts[i0], 1);
        atomicAdd(&g_counts[i1], 1);
    }
}

__global__ void scan_kernel() {
    if (threadIdx.x == 0) {
        int o = 0;
        for (int e = 0; e < NE; e++) { g_offs[e] = o; g_cursor[e] = o; o += g_counts[e]; }
        g_offs[NE] = o;
    }
}

__global__ void scatter_kernel() {
    int i = blockIdx.x * blockDim.x + threadIdx.x;
    if (i < NSLOT) {
        int e = g_top_idx[i];
        int pos = atomicAdd(&g_cursor[e], 1);
        g_slot_tok[pos] = i >> 1;
        g_tok_pos[i] = pos;
    }
}

// combine: out[t] = s0*down[pos0] + s1*down[pos1]
__global__ void combine_kernel(float* __restrict__ out) {
    int i = blockIdx.x * blockDim.x + threadIdx.x;
    int t  = i >> 9;           // HD/4 = 512 float4 per token
    int h4 = i & 511;
    float s0 = g_top_scale[2*t], s1 = g_top_scale[2*t+1];
    int p0 = g_tok_pos[2*t], p1 = g_tok_pos[2*t+1];
    float4 a = ((const float4*)(g_gbuf + (size_t)p0 * HD))[h4];
    float4 b = ((const float4*)(g_gbuf + (size_t)p1 * HD))[h4];
    float4 o;
    o.x = s0*a.x + s1*b.x; o.y = s0*a.y + s1*b.y;
    o.z = s0*a.z + s1*b.z; o.w = s0*a.w + s1*b.w;
    ((float4*)(out + (size_t)t * HD))[h4] = o;
}

// ---------------- fused gate+up GEMM + swiglu epilogue ----------------
// C_act[slot, n] = silu(x@w1) * (x@w3), 128x128 tile per CTA, dual B
__global__ void __launch_bounds__(512, 1)
gemm_gateup() {
    extern __shared__ __align__(128) char sm[];
    const int e = blockIdx.z;
    const int rowBeg = g_offs[e], rowEnd = g_offs[e+1];
    const int row0 = rowBeg + blockIdx.y * BM;
    if (row0 >= rowEnd) return;
    const int n0 = blockIdx.x * GU_BN;

    const __half* B1 = g_w1 + (size_t)e * HD * HD;
    const __half* B3 = g_w3 + (size_t)e * HD * HD;

    const int tid = threadIdx.x;
    const uint32_t sb = smem_u32(sm);

    // A: 1024 segs (128 rows x 8), 2 per thread
    const __half* aSrc[2]; int aSz[2]; uint32_t aDst[2];
#pragma unroll
    for (int i = 0; i < 2; i++) {
        int idx = i * 512 + tid, row = idx >> 3, seg = idx & 7;
        int aslot = row0 + row;
        bool av = aslot < rowEnd;
        int tok = av ? g_slot_tok[aslot] : 0;
        aSrc[i] = g_x16 + (size_t)tok * HD + seg * 8;
        aSz[i] = av ? 16 : 0;
        aDst[i] = (uint32_t)(row * 144 + seg * 16);
    }
    // B: per mat 1024 segs (64 rows x 16), 2 per thread per mat
    const __half* b1Src[2]; const __half* b3Src[2]; uint32_t bDst[2];
#pragma unroll
    for (int i = 0; i < 2; i++) {
        int idx = i * 512 + tid, row = idx >> 4, seg = idx & 15;
        b1Src[i] = B1 + (size_t)row * HD + n0 + seg * 8;
        b3Src[i] = B3 + (size_t)row * HD + n0 + seg * 8;
        bDst[i] = (uint32_t)(row * 272 + seg * 16);
    }

    auto load_stage = [&](int c, int stg) {
        uint32_t st = sb + (uint32_t)stg * GU_STG;
        size_t k0 = (size_t)c * BKC;
#pragma unroll
        for (int i = 0; i < 2; i++) cp16(st + GU_AA + aDst[i], aSrc[i] + k0, aSz[i]);
#pragma unroll
        for (int i = 0; i < 2; i++) {
            cp16(st + GU_B1 + bDst[i], b1Src[i] + k0 * HD, 16);
            cp16(st + GU_B2 + bDst[i], b3Src[i] + k0 * HD, 16);
        }
        cp_commit();
    };

    const int wid = tid >> 5, lane = tid & 31;
    const int wm = wid & 3, wn = wid >> 2;        // 4x4 warps, warp tile 32M x 32N (per mat)
    const int ar = lane & 15, ac = (lane >> 4) * 8;
    const int br = lane & 15, bc = (lane >> 4) * 8;

    float accG[2][4][4], accU[2][4][4];
#pragma unroll
    for (int mt = 0; mt < 2; mt++)
#pragma unroll
        for (int nt = 0; nt < 4; nt++)
#pragma unroll
            for (int q = 0; q < 4; q++) { accG[mt][nt][q] = 0.f; accU[mt][nt][q] = 0.f; }

    load_stage(0, 0);
    load_stage(1, 1);

    for (int c = 0; c < NCHUNK; c++) {
        if (c + 1 < NCHUNK) asm volatile("cp.async.wait_group 1;\n" ::: "memory");
        else                asm volatile("cp.async.wait_group 0;\n" ::: "memory");
        __syncthreads();
        if (c + 2 < NCHUNK) load_stage(c + 2, (c + 2) % NSTG);
        uint32_t stb = sb + (uint32_t)(c % NSTG) * GU_STG;

#pragma unroll
        for (int kk = 0; kk < 4; kk++) {
            uint32_t a[2][4];
#pragma unroll
            for (int mt = 0; mt < 2; mt++) {
                uint32_t aaddr = stb + GU_AA
                    + (uint32_t)((wm * 32 + mt * 16 + ar) * 144 + (kk * 16 + ac) * 2);
                ldsm_x4(a[mt], aaddr);
            }
            uint32_t brow = (uint32_t)((kk * 16 + br) * 272);
#pragma unroll
            for (int p = 0; p < 2; p++) {
                uint32_t coff = (uint32_t)((wn * 32 + p * 16 + bc) * 2);
                uint32_t b1[4], b3[4];
                ldsm_x4_t(b1, stb + GU_B1 + brow + coff);
                ldsm_x4_t(b3, stb + GU_B2 + brow + coff);
                mma16816(accG[0][2*p],   a[0], b1[0], b1[1]);
                mma16816(accG[0][2*p+1], a[0], b1[2], b1[3]);
                mma16816(accG[1][2*p],   a[1], b1[0], b1[1]);
                mma16816(accG[1][2*p+1], a[1], b1[2], b1[3]);
                mma16816(accU[0][2*p],   a[0], b3[0], b3[1]);
                mma16816(accU[0][2*p+1], a[0], b3[2], b3[3]);
                mma16816(accU[1][2*p],   a[1], b3[0], b3[1]);
                mma16816(accU[1][2*p+1], a[1], b3[2], b3[3]);
            }
        }
    }

    // epilogue: act = silu(g)*u -> fp16
    const int rIn = lane >> 2, cIn = (lane & 3) * 2;
#pragma unroll
    for (int mt = 0; mt < 2; mt++) {
#pragma unroll
        for (int half = 0; half < 2; half++) {
            int slot = row0 + wm * 32 + mt * 16 + rIn + half * 8;
            if (slot < rowEnd) {
                __half* Cp = g_act + (size_t)slot * HD + n0 + wn * 32 + cIn;
#pragma unroll
                for (int nt = 0; nt < 4; nt++) {
                    float a0 = silu_mul(accG[mt][nt][half*2],   accU[mt][nt][half*2]);
                    float a1 = silu_mul(accG[mt][nt][half*2+1], accU[mt][nt][half*2+1]);
                    *(__half2*)(Cp + nt * 8) = __floats2half2_rn(a0, a1);
                }
            }
        }
    }
}

// ---------------- down GEMM (act @ w2 -> gbuf fp32), 128x256 ----------------
__global__ void __launch_bounds__(512, 1)
gemm_down() {
    extern __shared__ __align__(128) char sm[];
    const int e = blockIdx.z;
    const int rowBeg = g_offs[e], rowEnd = g_offs[e+1];
    const int row0 = rowBeg + blockIdx.y * BM;
    if (row0 >= rowEnd) return;
    const int n0 = blockIdx.x * DN_BN;

    const __half* Bw = g_w2 + (size_t)e * HD * HD;
    const int tid = threadIdx.x;
    const uint32_t sb = smem_u32(sm);

    const __half* aSrc[2]; int aSz[2]; uint32_t aDst[2];
#pragma unroll
    for (int i = 0; i < 2; i++) {
        int idx = i * 512 + tid, row = idx >> 3, seg = idx & 7;
        int aslot = row0 + row;
        bool av = aslot < rowEnd;
        aSrc[i] = g_act + (size_t)(av ? aslot : 0) * HD + seg * 8;
        aSz[i] = av ? 16 : 0;
        aDst[i] = (uint32_t)(row * 144 + seg * 16);
    }
    const __half* bSrc[4]; uint32_t bDst[4];
#pragma unroll
    for (int i = 0; i < 4; i++) {
        int idx = i * 512 + tid, row = idx >> 5, seg = idx & 31;
        bSrc[i] = Bw + (size_t)row * HD + n0 + seg * 8;
        bDst[i] = (uint32_t)(row * 528 + seg * 16);
    }

    auto load_stage = [&](int c, int stg) {
        uint32_t st = sb + (uint32_t)stg * DN_STG;
        size_t k0 = (size_t)c * BKC;
#pragma unroll
        for (int i = 0; i < 2; i++) cp16(st + DN_AA + aDst[i], aSrc[i] + k0, aSz[i]);
#pragma unroll
        for (int i = 0; i < 4; i++) cp16(st + DN_BB + bDst[i], bSrc[i] + k0 * HD, 16);
        cp_commit();
    };

    const int wid = tid >> 5, lane = tid & 31;
    const int wm = wid & 3, wn = wid >> 2;
    const int ar = lane & 15, ac = (lane >> 4) * 8;
    const int br = lane & 15, bc = (lane >> 4) * 8;

    float acc[2][8][4];
#pragma unroll
    for (int mt = 0; mt < 2; mt++)
#pragma unroll
        for (int nt = 0; nt < 8; nt++)
#pragma unroll
            for (int q = 0; q < 4; q++) acc[mt][nt][q] = 0.f;

    load_stage(0, 0);
    load_stage(1, 1);

    for (int c = 0; c < NCHUNK; c++) {
        if (c + 1 < NCHUNK) asm volatile("cp.async.wait_group 1;\n" ::: "memory");
        else                asm volatile("cp.async.wait_group 0;\n" ::: "memory");
        __syncthreads();
        if (c + 2 < NCHUNK) load_stage(c + 2, (c + 2) % NSTG);
        uint32_t stb = sb + (uint32_t)(c % NSTG) * DN_STG;

#pragma unroll
        for (int kk = 0; kk < 4; kk++) {
            uint32_t a[2][4];
#pragma unroll
            for (int mt = 0; mt < 2; mt++) {
                uint32_t aaddr = stb + DN_AA
                    + (uint32_t)((wm * 32 + mt * 16 + ar) * 144 + (kk * 16 + ac) * 2);
                ldsm_x4(a[mt], aaddr);
            }
#pragma unroll
            for (int p = 0; p < 4; p++) {
                uint32_t b[4];
                uint32_t baddr = stb + DN_BB
                    + (uint32_t)((kk * 16 + br) * 528 + (wn * 64 + p * 16 + bc) * 2);
                ldsm_x4_t(b, baddr);
                mma16816(acc[0][2*p],   a[0], b[0], b[1]);
                mma16816(acc[0][2*p+1], a[0], b[2], b[3]);
                mma16816(acc[1][2*p],   a[1], b[0], b[1]);
                mma16816(acc[1][2*p+1], a[1], b[2], b[3]);
            }
        }
    }

    const int rIn = lane >> 2, cIn = (lane & 3) * 2;
#pragma unroll
    for (int mt = 0; mt < 2; mt++) {
#pragma unroll
        for (int half = 0; half < 2; half++) {
            int slot = row0 + wm * 32 + mt * 16 + rIn + half * 8;
            if (slot < rowEnd) {
                float* Cp = g_gbuf + (size_t)slot * HD + n0 + wn * 64 + cIn;
#pragma unroll
                for (int nt = 0; nt < 8; nt++) {
                    float2 v = make_float2(acc[mt][nt][half*2], acc[mt][nt][half*2+1]);
                    *(float2*)(Cp + nt * 8) = v;
                }
            }
        }
    }
}

// ---------------- host launcher ----------------
extern "C" void kernel_launch(void* const* d_in, const int* in_sizes, int n_in,
                              void* d_out, int out_size) {
    const float* x  = (const float*)d_in[0];
    const float* rw = (const float*)d_in[1];
    const float* w1 = (const float*)d_in[2];
    const float* w3 = (const float*)d_in[3];
    const float* w2 = (const float*)d_in[4];
    float* out = (float*)d_out;

    cudaFuncSetAttribute(gemm_gateup, cudaFuncAttributeMaxDynamicSharedMemorySize, GU_SMEM);
    cudaFuncSetAttribute(gemm_down,   cudaFuncAttributeMaxDynamicSharedMemorySize, DN_SMEM);

    init_small_kernel<<<1, 32>>>();

    cvt_x_kernel<<<1024, 256>>>(x);
    cvt_w_all<<<dim3(2048, 3), 256>>>(w1, w3, w2);

    router_kernel<<<TTOK / 8, 256>>>(x, rw);
    scan_kernel<<<1, 32>>>();
    scatter_kernel<<<NSLOT / 256, 256>>>();

    dim3 ggu(HD/GU_BN, NSLOT/BM, NE);
    gemm_gateup<<<ggu, 512, GU_SMEM>>>();

    dim3 gd(HD/DN_BN, NSLOT/BM, NE);
    gemm_down<<<gd, 512, DN_SMEM>>>();

    combine_kernel<<<(TTOK * HD / 4) / 256, 256>>>(out);
}

// round 8
// speedup vs baseline: 2.7232x; 1.0459x over previous
#include <cuda_runtime.h>
#include <cuda_fp16.h>
#include <cstdint>
#include <cstddef>

// Problem constants: T=4096, H=I=2048, E=8, top-2
#define TTOK 4096
#define HD   2048
#define NE   8
#define NSLOT (2*TTOK)

#define BM 128
#define BKC 64
#define NCHUNK (HD/BKC)     // 32
#define NSTG 3

// ---- fused gate+up GEMM tile: 128(M) x 128(N), dual-B ----
#define GU_BN 128
#define GU_AA 0                 // A: 128 rows x 144B stride = 18432
#define GU_B1 18432             // B1: 64 rows x 272B stride = 17408
#define GU_B2 35840             // B2: 17408
#define GU_STG 53248
#define GU_SMEM (NSTG*GU_STG)   // 159744

// ---- down GEMM tile: 128(M) x 256(N) ----
#define DN_BN 256
#define DN_AA 0                 // A: 128 rows x 144B stride = 18432
#define DN_BB 18432             // B: 64 rows x 528B stride = 33792
#define DN_STG 52224
#define DN_SMEM (NSTG*DN_STG)   // 156672

// ---- prep kernel block partition ----
#define NBW 6144                // weight-convert blocks (2048 per tensor)
#define NBX 512                 // x-convert blocks
#define NBR 128                 // router blocks (8 warps x 4 tokens = 32 tok/blk)
#define NB_PREP (NBW + NBX + NBR)

// ---------------- device scratch ----------------
__device__ int   g_counts[NE];
__device__ int   g_offs[NE+1];
__device__ int   g_cursor[NE];
__device__ int   g_top_idx[NSLOT];
__device__ float g_top_scale[NSLOT];
__device__ int   g_slot_tok[NSLOT];
__device__ int   g_tok_pos[NSLOT];

__device__ __align__(16) __half g_x16[(size_t)TTOK*HD];
__device__ __align__(16) __half g_w1[(size_t)NE*HD*HD];   // [e][k][n] fp16
__device__ __align__(16) __half g_w3[(size_t)NE*HD*HD];
__device__ __align__(16) __half g_w2[(size_t)NE*HD*HD];
__device__ __align__(16) __half g_act[(size_t)NSLOT*HD];  // silu(gate)*up (fp16)
__device__ __align__(16) float  g_gbuf[(size_t)NSLOT*HD]; // down out (fp32)

// ---------------- helpers ----------------
__device__ __forceinline__ uint32_t smem_u32(const void* p) {
    return (uint32_t)__cvta_generic_to_shared(p);
}
__device__ __forceinline__ void cp16(uint32_t dst, const void* src, int szbytes) {
    asm volatile("cp.async.cg.shared.global [%0], [%1], 16, %2;\n"
                 :: "r"(dst), "l"(src), "r"(szbytes));
}
__device__ __forceinline__ void cp_commit() {
    asm volatile("cp.async.commit_group;\n");
}
__device__ __forceinline__ void ldsm_x4(uint32_t (&r)[4], uint32_t addr) {
    asm volatile("ldmatrix.sync.aligned.m8n8.x4.shared.b16 {%0,%1,%2,%3}, [%4];\n"
                 : "=r"(r[0]), "=r"(r[1]), "=r"(r[2]), "=r"(r[3]) : "r"(addr));
}
__device__ __forceinline__ void ldsm_x4_t(uint32_t (&r)[4], uint32_t addr) {
    asm volatile("ldmatrix.sync.aligned.m8n8.x4.trans.shared.b16 {%0,%1,%2,%3}, [%4];\n"
                 : "=r"(r[0]), "=r"(r[1]), "=r"(r[2]), "=r"(r[3]) : "r"(addr));
}
__device__ __forceinline__ void mma16816(float (&c)[4], const uint32_t (&a)[4],
                                         uint32_t b0, uint32_t b1) {
    asm volatile(
        "mma.sync.aligned.m16n8k16.row.col.f32.f16.f16.f32 "
        "{%0,%1,%2,%3}, {%4,%5,%6,%7}, {%8,%9}, {%0,%1,%2,%3};\n"
        : "+f"(c[0]), "+f"(c[1]), "+f"(c[2]), "+f"(c[3])
        : "r"(a[0]), "r"(a[1]), "r"(a[2]), "r"(a[3]), "r"(b0), "r"(b1));
}
__device__ __forceinline__ float silu_mul(float g, float u) {
    return u * (g / (1.f + __expf(-g)));
}

// ---------------- setup ----------------
__global__ void init_small_kernel() {
    int i = threadIdx.x;
    if (i < NE) { g_counts[i] = 0; g_cursor[i] = 0; }
}

// Fused prep: weight converts + x convert + router in ONE launch.
// Latency-bound router blocks hide under HBM-bound convert blocks.
__global__ void __launch_bounds__(256)
prep_kernel(const float* __restrict__ x,  const float* __restrict__ rw,
            const float* __restrict__ w1, const float* __restrict__ w3,
            const float* __restrict__ w2) {
    const int bx = blockIdx.x;
    const int tid = threadIdx.x;

    if (bx < NBW) {
        // ---- weight convert: fp32 -> fp16, 3 tensors x 2048 blocks ----
        const int which = bx >> 11;            // /2048
        const int lb = bx & 2047;
        const float* src = (which == 0) ? w1 : (which == 1) ? w3 : w2;
        __half* d = (which == 0) ? g_w1 : (which == 1) ? g_w3 : g_w2;
        const size_t n4 = ((size_t)NE * HD * HD) >> 2;
        const float4* s4 = (const float4*)src;
        __half2* d2 = (__half2*)d;
        const size_t stride = (size_t)2048 * 256;
        for (size_t i = (size_t)lb * 256 + tid; i < n4; i += stride) {
            float4 v = s4[i];
            d2[2*i]   = __floats2half2_rn(v.x, v.y);
            d2[2*i+1] = __floats2half2_rn(v.z, v.w);
        }
    } else if (bx < NBW + NBX) {
        // ---- x convert: fp32 -> fp16 ----
        const int lb = bx - NBW;
        const size_t n4 = ((size_t)TTOK * HD) >> 2;
        const float4* s4 = (const float4*)x;
        __half2* d2 = (__half2*)g_x16;
        const size_t stride = (size_t)NBX * 256;
        for (size_t i = (size_t)lb * 256 + tid; i < n4; i += stride) {
            float4 v = s4[i];
            d2[2*i]   = __floats2half2_rn(v.x, v.y);
            d2[2*i+1] = __floats2half2_rn(v.z, v.w);
        }
    } else {
        // ---- router: 8 warps/block, 4 tokens/warp ----
        const int bi = bx - (NBW + NBX);
        const int warp = tid >> 5, lane = tid & 31;
        const int t0 = (bi * 8 + warp) * 4;
        float acc[4][NE];
#pragma unroll
        for (int j = 0; j < 4; j++)
#pragma unroll
            for (int e = 0; e < NE; e++) acc[j][e] = 0.f;

        const float* xr = x + (size_t)t0 * HD;
        for (int h = lane; h < HD; h += 32) {
            float4 r0 = *(const float4*)(rw + (size_t)h * NE);
            float4 r1 = *(const float4*)(rw + (size_t)h * NE + 4);
            float rv[NE] = {r0.x, r0.y, r0.z, r0.w, r1.x, r1.y, r1.z, r1.w};
#pragma unroll
            for (int j = 0; j < 4; j++) {
                float xv = xr[(size_t)j * HD + h];
#pragma unroll
                for (int e = 0; e < NE; e++) acc[j][e] = fmaf(xv, rv[e], acc[j][e]);
            }
        }
#pragma unroll
        for (int j = 0; j < 4; j++)
#pragma unroll
            for (int e = 0; e < NE; e++) {
#pragma unroll
                for (int o = 16; o; o >>= 1)
                    acc[j][e] += __shfl_xor_sync(0xffffffffu, acc[j][e], o);
            }
        if (lane == 0) {
#pragma unroll
            for (int j = 0; j < 4; j++) {
                int t = t0 + j;
                int i0 = 0; float v0 = acc[j][0];
#pragma unroll
                for (int e = 1; e < NE; e++) if (acc[j][e] > v0) { v0 = acc[j][e]; i0 = e; }
                int i1 = -1; float v1 = -3.4e38f;
#pragma unroll
                for (int e = 0; e < NE; e++)
                    if (e != i0 && acc[j][e] > v1) { v1 = acc[j][e]; i1 = e; }
                float ex = expf(v1 - v0);
                float inv = 1.f / (1.f + ex);
                g_top_idx[2*t]   = i0; g_top_scale[2*t]   = inv;
                g_top_idx[2*t+1] = i1; g_top_scale[2*t+1] = ex * inv;
                atomicAdd(&g_counts[i0], 1);
                atomicAdd(&g_counts[i1], 1);
            }
        }
    }
}

// scan + scatter fused: single block
__global__ void __launch_bounds__(1024)
scan_scatter_kernel() {
    if (threadIdx.x == 0) {
        int o = 0;
        for (int e = 0; e < NE; e++) { g_offs[e] = o; g_cursor[e] = o; o += g_counts[e]; }
        g_offs[NE] = o;
    }
    __syncthreads();
    for (int i = threadIdx.x; i < NSLOT; i += 1024) {
        int e = g_top_idx[i];
        int pos = atomicAdd(&g_cursor[e], 1);
        g_slot_tok[pos] = i >> 1;
        g_tok_pos[i] = pos;
    }
}

// combine: out[t] = s0*down[pos0] + s1*down[pos1]
__global__ void combine_kernel(float* __restrict__ out) {
    int i = blockIdx.x * blockDim.x + threadIdx.x;
    int t  = i >> 9;           // HD/4 = 512 float4 per token
    int h4 = i & 511;
    float s0 = g_top_scale[2*t], s1 = g_top_scale[2*t+1];
    int p0 = g_tok_pos[2*t], p1 = g_tok_pos[2*t+1];
    float4 a = ((const float4*)(g_gbuf + (size_t)p0 * HD))[h4];
    float4 b = ((const float4*)(g_gbuf + (size_t)p1 * HD))[h4];
    float4 o;
    o.x = s0*a.x + s1*b.x; o.y = s0*a.y + s1*b.y;
    o.z = s0*a.z + s1*b.z; o.w = s0*a.w + s1*b.w;
    ((float4*)(out + (size_t)t * HD))[h4] = o;
}

// ---------------- fused gate+up GEMM + swiglu epilogue ----------------
__global__ void __launch_bounds__(512, 1)
gemm_gateup() {
    extern __shared__ __align__(128) char sm[];
    const int e = blockIdx.z;
    const int rowBeg = g_offs[e], rowEnd = g_offs[e+1];
    const int row0 = rowBeg + blockIdx.y * BM;
    if (row0 >= rowEnd) return;
    const int n0 = blockIdx.x * GU_BN;

    const __half* B1 = g_w1 + (size_t)e * HD * HD;
    const __half* B3 = g_w3 + (size_t)e * HD * HD;

    const int tid = threadIdx.x;
    const uint32_t sb = smem_u32(sm);

    const __half* aSrc[2]; int aSz[2]; uint32_t aDst[2];
#pragma unroll
    for (int i = 0; i < 2; i++) {
        int idx = i * 512 + tid, row = idx >> 3, seg = idx & 7;
        int aslot = row0 + row;
        bool av = aslot < rowEnd;
        int tok = av ? g_slot_tok[aslot] : 0;
        aSrc[i] = g_x16 + (size_t)tok * HD + seg * 8;
        aSz[i] = av ? 16 : 0;
        aDst[i] = (uint32_t)(row * 144 + seg * 16);
    }
    const __half* b1Src[2]; const __half* b3Src[2]; uint32_t bDst[2];
#pragma unroll
    for (int i = 0; i < 2; i++) {
        int idx = i * 512 + tid, row = idx >> 4, seg = idx & 15;
        b1Src[i] = B1 + (size_t)row * HD + n0 + seg * 8;
        b3Src[i] = B3 + (size_t)row * HD + n0 + seg * 8;
        bDst[i] = (uint32_t)(row * 272 + seg * 16);
    }

    auto load_stage = [&](int c, int stg) {
        uint32_t st = sb + (uint32_t)stg * GU_STG;
        size_t k0 = (size_t)c * BKC;
#pragma unroll
        for (int i = 0; i < 2; i++) cp16(st + GU_AA + aDst[i], aSrc[i] + k0, aSz[i]);
#pragma unroll
        for (int i = 0; i < 2; i++) {
            cp16(st + GU_B1 + bDst[i], b1Src[i] + k0 * HD, 16);
            cp16(st + GU_B2 + bDst[i], b3Src[i] + k0 * HD, 16);
        }
        cp_commit();
    };

    const int wid = tid >> 5, lane = tid & 31;
    const int wm = wid & 3, wn = wid >> 2;
    const int ar = lane & 15, ac = (lane >> 4) * 8;
    const int br = lane & 15, bc = (lane >> 4) * 8;

    float accG[2][4][4], accU[2][4][4];
#pragma unroll
    for (int mt = 0; mt < 2; mt++)
#pragma unroll
        for (int nt = 0; nt < 4; nt++)
#pragma unroll
            for (int q = 0; q < 4; q++) { accG[mt][nt][q] = 0.f; accU[mt][nt][q] = 0.f; }

    load_stage(0, 0);
    load_stage(1, 1);

    for (int c = 0; c < NCHUNK; c++) {
        if (c + 1 < NCHUNK) asm volatile("cp.async.wait_group 1;\n" ::: "memory");
        else                asm volatile("cp.async.wait_group 0;\n" ::: "memory");
        __syncthreads();
        if (c + 2 < NCHUNK) load_stage(c + 2, (c + 2) % NSTG);
        uint32_t stb = sb + (uint32_t)(c % NSTG) * GU_STG;

#pragma unroll
        for (int kk = 0; kk < 4; kk++) {
            uint32_t a[2][4];
#pragma unroll
            for (int mt = 0; mt < 2; mt++) {
                uint32_t aaddr = stb + GU_AA
                    + (uint32_t)((wm * 32 + mt * 16 + ar) * 144 + (kk * 16 + ac) * 2);
                ldsm_x4(a[mt], aaddr);
            }
            uint32_t brow = (uint32_t)((kk * 16 + br) * 272);
#pragma unroll
            for (int p = 0; p < 2; p++) {
                uint32_t coff = (uint32_t)((wn * 32 + p * 16 + bc) * 2);
                uint32_t b1[4], b3[4];
                ldsm_x4_t(b1, stb + GU_B1 + brow + coff);
                ldsm_x4_t(b3, stb + GU_B2 + brow + coff);
                mma16816(accG[0][2*p],   a[0], b1[0], b1[1]);
                mma16816(accG[0][2*p+1], a[0], b1[2], b1[3]);
                mma16816(accG[1][2*p],   a[1], b1[0], b1[1]);
                mma16816(accG[1][2*p+1], a[1], b1[2], b1[3]);
                mma16816(accU[0][2*p],   a[0], b3[0], b3[1]);
                mma16816(accU[0][2*p+1], a[0], b3[2], b3[3]);
                mma16816(accU[1][2*p],   a[1], b3[0], b3[1]);
                mma16816(accU[1][2*p+1], a[1], b3[2], b3[3]);
            }
        }
    }

    const int rIn = lane >> 2, cIn = (lane & 3) * 2;
#pragma unroll
    for (int mt = 0; mt < 2; mt++) {
#pragma unroll
        for (int half = 0; half < 2; half++) {
            int slot = row0 + wm * 32 + mt * 16 + rIn + half * 8;
            if (slot < rowEnd) {
                __half* Cp = g_act + (size_t)slot * HD + n0 + wn * 32 + cIn;
#pragma unroll
                for (int nt = 0; nt < 4; nt++) {
                    float a0 = silu_mul(accG[mt][nt][half*2],   accU[mt][nt][half*2]);
                    float a1 = silu_mul(accG[mt][nt][half*2+1], accU[mt][nt][half*2+1]);
                    *(__half2*)(Cp + nt * 8) = __floats2half2_rn(a0, a1);
                }
            }
        }
    }
}

// ---------------- down GEMM (act @ w2 -> gbuf fp32), 128x256 ----------------
__global__ void __launch_bounds__(512, 1)
gemm_down() {
    extern __shared__ __align__(128) char sm[];
    const int e = blockIdx.z;
    const int rowBeg = g_offs[e], rowEnd = g_offs[e+1];
    const int row0 = rowBeg + blockIdx.y * BM;
    if (row0 >= rowEnd) return;
    const int n0 = blockIdx.x * DN_BN;

    const __half* Bw = g_w2 + (size_t)e * HD * HD;
    const int tid = threadIdx.x;
    const uint32_t sb = smem_u32(sm);

    const __half* aSrc[2]; int aSz[2]; uint32_t aDst[2];
#pragma unroll
    for (int i = 0; i < 2; i++) {
        int idx = i * 512 + tid, row = idx >> 3, seg = idx & 7;
        int aslot = row0 + row;
        bool av = aslot < rowEnd;
        aSrc[i] = g_act + (size_t)(av ? aslot : 0) * HD + seg * 8;
        aSz[i] = av ? 16 : 0;
        aDst[i] = (uint32_t)(row * 144 + seg * 16);
    }
    const __half* bSrc[4]; uint32_t bDst[4];
#pragma unroll
    for (int i = 0; i < 4; i++) {
        int idx = i * 512 + tid, row = idx >> 5, seg = idx & 31;
        bSrc[i] = Bw + (size_t)row * HD + n0 + seg * 8;
        bDst[i] = (uint32_t)(row * 528 + seg * 16);
    }

    auto load_stage = [&](int c, int stg) {
        uint32_t st = sb + (uint32_t)stg * DN_STG;
        size_t k0 = (size_t)c * BKC;
#pragma unroll
        for (int i = 0; i < 2; i++) cp16(st + DN_AA + aDst[i], aSrc[i] + k0, aSz[i]);
#pragma unroll
        for (int i = 0; i < 4; i++) cp16(st + DN_BB + bDst[i], bSrc[i] + k0 * HD, 16);
        cp_commit();
    };

    const int wid = tid >> 5, lane = tid & 31;
    const int wm = wid & 3, wn = wid >> 2;
    const int ar = lane & 15, ac = (lane >> 4) * 8;
    const int br = lane & 15, bc = (lane >> 4) * 8;

    float acc[2][8][4];
#pragma unroll
    for (int mt = 0; mt < 2; mt++)
#pragma unroll
        for (int nt = 0; nt < 8; nt++)
#pragma unroll
            for (int q = 0; q < 4; q++) acc[mt][nt][q] = 0.f;

    load_stage(0, 0);
    load_stage(1, 1);

    for (int c = 0; c < NCHUNK; c++) {
        if (c + 1 < NCHUNK) asm volatile("cp.async.wait_group 1;\n" ::: "memory");
        else                asm volatile("cp.async.wait_group 0;\n" ::: "memory");
        __syncthreads();
        if (c + 2 < NCHUNK) load_stage(c + 2, (c + 2) % NSTG);
        uint32_t stb = sb + (uint32_t)(c % NSTG) * DN_STG;

#pragma unroll
        for (int kk = 0; kk < 4; kk++) {
            uint32_t a[2][4];
#pragma unroll
            for (int mt = 0; mt < 2; mt++) {
                uint32_t aaddr = stb + DN_AA
                    + (uint32_t)((wm * 32 + mt * 16 + ar) * 144 + (kk * 16 + ac) * 2);
                ldsm_x4(a[mt], aaddr);
            }
#pragma unroll
            for (int p = 0; p < 4; p++) {
                uint32_t b[4];
                uint32_t baddr = stb + DN_BB
                    + (uint32_t)((kk * 16 + br) * 528 + (wn * 64 + p * 16 + bc) * 2);
                ldsm_x4_t(b, baddr);
                mma16816(acc[0][2*p],   a[0], b[0], b[1]);
                mma16816(acc[0][2*p+1], a[0], b[2], b[3]);
                mma16816(acc[1][2*p],   a[1], b[0], b[1]);
                mma16816(acc[1][2*p+1], a[1], b[2], b[3]);
            }
        }
    }

    const int rIn = lane >> 2, cIn = (lane & 3) * 2;
#pragma unroll
    for (int mt = 0; mt < 2; mt++) {
#pragma unroll
        for (int half = 0; half < 2; half++) {
            int slot = row0 + wm * 32 + mt * 16 + rIn + half * 8;
            if (slot < rowEnd) {
                float* Cp = g_gbuf + (size_t)slot * HD + n0 + wn * 64 + cIn;
#pragma unroll
                for (int nt = 0; nt < 8; nt++) {
                    float2 v = make_float2(acc[mt][nt][half*2], acc[mt][nt][half*2+1]);
                    *(float2*)(Cp + nt * 8) = v;
                }
            }
        }
    }
}

// ---------------- host launcher ----------------
extern "C" void kernel_launch(void* const* d_in, const int* in_sizes, int n_in,
                              void* d_out, int out_size) {
    const float* x  = (const float*)d_in[0];
    const float* rw = (const float*)d_in[1];
    const float* w1 = (const float*)d_in[2];
    const float* w3 = (const float*)d_in[3];
    const float* w2 = (const float*)d_in[4];
    float* out = (float*)d_out;

    cudaFuncSetAttribute(gemm_gateup, cudaFuncAttributeMaxDynamicSharedMemorySize, GU_SMEM);
    cudaFuncSetAttribute(gemm_down,   cudaFuncAttributeMaxDynamicSharedMemorySize, DN_SMEM);

    init_small_kernel<<<1, 32>>>();
    prep_kernel<<<NB_PREP, 256>>>(x, rw, w1, w3, w2);
    scan_scatter_kernel<<<1, 1024>>>();

    dim3 ggu(HD/GU_BN, NSLOT/BM, NE);
    gemm_gateup<<<ggu, 512, GU_SMEM>>>();

    dim3 gd(HD/DN_BN, NSLOT/BM, NE);
    gemm_down<<<gd, 512, DN_SMEM>>>();

    combine_kernel<<<(TTOK * HD / 4) / 256, 256>>>(out);
}

// round 9
// speedup vs baseline: 3.0681x; 1.1266x over previous
#include <cuda_runtime.h>
#include <cuda_fp16.h>
#include <cstdint>
#include <cstddef>

// Problem constants: T=4096, H=I=2048, E=8, top-2
#define TTOK 4096
#define HD   2048
#define NE   8
#define NSLOT (2*TTOK)
#define NSLOTP 9216            // expert segments padded to 128 -> max 8192+8*127 -> 9216
#define MTMAX (NSLOTP/128)     // 72 M-tiles

#define BM 128
#define BKC 64
#define NCHUNK (HD/BKC)        // 32
#define NSTG 3

// gate+up: 128M x 128N dual-B
#define GU_ABLK 18432          // 128 rows x 144B
#define GU_BBLK 17408          // 64 rows x 272B
#define GU_STG  (GU_ABLK + 2*GU_BBLK)   // 53248
#define GU_SMEM (NSTG*GU_STG)           // 159744
// down: 128M x 256N
#define DN_ABLK 18432
#define DN_BBLK 33792          // 64 rows x 528B
#define DN_STG  (DN_ABLK + DN_BBLK)     // 52224
#define DN_SMEM (NSTG*DN_STG)           // 156672

// prep partition
#define NBW 6144
#define NBX 512
#define NBR 128
#define NB_PREP (NBW + NBX + NBR)

// ---------------- device scratch ----------------
__device__ int   g_counts[NE];
__device__ int   g_offs[NE];       // padded (128-aligned) segment starts
__device__ int   g_ends[NE];       // offs[e] + counts[e]
__device__ int   g_cursor[NE];
__device__ int   g_top_idx[NSLOT];
__device__ float g_top_scale[NSLOT];
__device__ int   g_slot_tok[NSLOTP];   // -1 for padding slots
__device__ int   g_tok_pos[NSLOT];

__device__ __align__(16) __half g_x16[(size_t)TTOK*HD];
// tile-blocked weights: GU blocks 64k x (128n + 8 pad) halves, DN blocks 64k x (256n + 8 pad)
__device__ __align__(16) __half g_w1t[(size_t)NE*16*32*(GU_BBLK/2)];
__device__ __align__(16) __half g_w3t[(size_t)NE*16*32*(GU_BBLK/2)];
__device__ __align__(16) __half g_w2t[(size_t)NE*8*32*(DN_BBLK/2)];
// slot-tiled activations: per (mtile, chunk): 128 rows x 144B
__device__ __align__(16) __half g_xg[(size_t)MTMAX*32*(GU_ABLK/2)];
__device__ __align__(16) __half g_actt[(size_t)MTMAX*32*(DN_ABLK/2)];
__device__ __align__(16) float  g_gbuf[(size_t)NSLOTP*HD];

// ---------------- helpers ----------------
__device__ __forceinline__ uint32_t smem_u32(const void* p) {
    return (uint32_t)__cvta_generic_to_shared(p);
}
__device__ __forceinline__ void mbar_init(uint32_t a, uint32_t cnt) {
    asm volatile("mbarrier.init.shared.b64 [%0], %1;" :: "r"(a), "r"(cnt) : "memory");
}
__device__ __forceinline__ void mbar_expect(uint32_t a, uint32_t bytes) {
    asm volatile("mbarrier.arrive.expect_tx.shared.b64 _, [%0], %1;"
                 :: "r"(a), "r"(bytes) : "memory");
}
__device__ __forceinline__ void mbar_wait(uint32_t a, uint32_t parity) {
    asm volatile(
        "{\n\t.reg .pred P;\n\t"
        "WL_%=:\n\t"
        "mbarrier.try_wait.parity.shared::cta.b64 P, [%0], %1;\n\t"
        "@P bra WD_%=;\n\t"
        "bra WL_%=;\n\t"
        "WD_%=:\n\t}"
        :: "r"(a), "r"(parity) : "memory");
}
__device__ __forceinline__ void bulk_g2s(uint32_t dst, const void* src,
                                         uint32_t bytes, uint32_t mbar) {
    asm volatile(
        "cp.async.bulk.shared::cta.global.mbarrier::complete_tx::bytes [%0], [%1], %2, [%3];"
        :: "r"(dst), "l"(src), "r"(bytes), "r"(mbar) : "memory");
}
__device__ __forceinline__ void ldsm_x4(uint32_t (&r)[4], uint32_t addr) {
    asm volatile("ldmatrix.sync.aligned.m8n8.x4.shared.b16 {%0,%1,%2,%3}, [%4];\n"
                 : "=r"(r[0]), "=r"(r[1]), "=r"(r[2]), "=r"(r[3]) : "r"(addr));
}
__device__ __forceinline__ void ldsm_x4_t(uint32_t (&r)[4], uint32_t addr) {
    asm volatile("ldmatrix.sync.aligned.m8n8.x4.trans.shared.b16 {%0,%1,%2,%3}, [%4];\n"
                 : "=r"(r[0]), "=r"(r[1]), "=r"(r[2]), "=r"(r[3]) : "r"(addr));
}
__device__ __forceinline__ void mma16816(float (&c)[4], const uint32_t (&a)[4],
                                         uint32_t b0, uint32_t b1) {
    asm volatile(
        "mma.sync.aligned.m16n8k16.row.col.f32.f16.f16.f32 "
        "{%0,%1,%2,%3}, {%4,%5,%6,%7}, {%8,%9}, {%0,%1,%2,%3};\n"
        : "+f"(c[0]), "+f"(c[1]), "+f"(c[2]), "+f"(c[3])
        : "r"(a[0]), "r"(a[1]), "r"(a[2]), "r"(a[3]), "r"(b0), "r"(b1));
}
__device__ __forceinline__ float silu_mul(float g, float u) {
    return u * (g / (1.f + __expf(-g)));
}
__device__ __forceinline__ uint32_t h2u(__half2 h) { return *(uint32_t*)&h; }

// ---------------- setup ----------------
__global__ void init_small_kernel() {
    int i = threadIdx.x;
    if (i < NE) { g_counts[i] = 0; g_cursor[i] = 0; }
}

// Fused prep: tiled weight converts + x convert + router in ONE launch.
__global__ void __launch_bounds__(256)
prep_kernel(const float* __restrict__ x,  const float* __restrict__ rw,
            const float* __restrict__ w1, const float* __restrict__ w3,
            const float* __restrict__ w2) {
    const int bx = blockIdx.x;
    const int tid = threadIdx.x;

    if (bx < NBW) {
        // ---- weight convert into tile-blocked fp16 layouts ----
        const int which = bx >> 11;            // 0:w1 1:w3 2:w2
        const int lb = bx & 2047;
        const float* src = (which == 0) ? w1 : (which == 1) ? w3 : w2;
        const size_t U = (size_t)NE * HD * HD / 8;   // 16B units (8 n each)
        const size_t stride = (size_t)2048 * 256;
        for (size_t u = (size_t)lb * 256 + tid; u < U; u += stride) {
            int n8 = (int)(u & 255);           // n = n8*8
            size_t ek = u >> 8;                // e*2048 + k
            int k = (int)(ek & 2047);
            int e = (int)(ek >> 11);
            const float4* s = (const float4*)src + ek * 512 + n8 * 2;
            float4 v0 = s[0], v1 = s[1];
            uint4 pkt;
            pkt.x = h2u(__floats2half2_rn(v0.x, v0.y));
            pkt.y = h2u(__floats2half2_rn(v0.z, v0.w));
            pkt.z = h2u(__floats2half2_rn(v1.x, v1.y));
            pkt.w = h2u(__floats2half2_rn(v1.z, v1.w));
            char* dst;
            if (which < 2) {   // GU layout: 16 N-tiles of 128, row stride 272B
                int nt = n8 >> 4, nl = n8 & 15;
                char* base = (char*)((which == 0) ? g_w1t : g_w3t);
                dst = base + ((size_t)((e*16 + nt)*32 + (k >> 6)))*GU_BBLK
                      + (size_t)(k & 63)*272 + (size_t)nl*16;
            } else {           // DN layout: 8 N-tiles of 256, row stride 528B
                int nt = n8 >> 5, nl = n8 & 31;
                dst = (char*)g_w2t + ((size_t)((e*8 + nt)*32 + (k >> 6)))*DN_BBLK
                      + (size_t)(k & 63)*528 + (size_t)nl*16;
            }
            *(uint4*)dst = pkt;
        }
    } else if (bx < NBW + NBX) {
        // ---- x convert: fp32 -> fp16 ----
        const int lb = bx - NBW;
        const size_t n4 = ((size_t)TTOK * HD) >> 2;
        const float4* s4 = (const float4*)x;
        __half2* d2 = (__half2*)g_x16;
        const size_t stride = (size_t)NBX * 256;
        for (size_t i = (size_t)lb * 256 + tid; i < n4; i += stride) {
            float4 v = s4[i];
            d2[2*i]   = __floats2half2_rn(v.x, v.y);
            d2[2*i+1] = __floats2half2_rn(v.z, v.w);
        }
    } else {
        // ---- router: 8 warps/block, 4 tokens/warp ----
        const int bi = bx - (NBW + NBX);
        const int warp = tid >> 5, lane = tid & 31;
        const int t0 = (bi * 8 + warp) * 4;
        float acc[4][NE];
#pragma unroll
        for (int j = 0; j < 4; j++)
#pragma unroll
            for (int e = 0; e < NE; e++) acc[j][e] = 0.f;

        const float* xr = x + (size_t)t0 * HD;
        for (int h = lane; h < HD; h += 32) {
            float4 r0 = *(const float4*)(rw + (size_t)h * NE);
            float4 r1 = *(const float4*)(rw + (size_t)h * NE + 4);
            float rv[NE] = {r0.x, r0.y, r0.z, r0.w, r1.x, r1.y, r1.z, r1.w};
#pragma unroll
            for (int j = 0; j < 4; j++) {
                float xv = xr[(size_t)j * HD + h];
#pragma unroll
                for (int e = 0; e < NE; e++) acc[j][e] = fmaf(xv, rv[e], acc[j][e]);
            }
        }
#pragma unroll
        for (int j = 0; j < 4; j++)
#pragma unroll
            for (int e = 0; e < NE; e++) {
#pragma unroll
                for (int o = 16; o; o >>= 1)
                    acc[j][e] += __shfl_xor_sync(0xffffffffu, acc[j][e], o);
            }
        if (lane == 0) {
#pragma unroll
            for (int j = 0; j < 4; j++) {
                int t = t0 + j;
                int i0 = 0; float v0 = acc[j][0];
#pragma unroll
                for (int e = 1; e < NE; e++) if (acc[j][e] > v0) { v0 = acc[j][e]; i0 = e; }
                int i1 = -1; float v1 = -3.4e38f;
#pragma unroll
                for (int e = 0; e < NE; e++)
                    if (e != i0 && acc[j][e] > v1) { v1 = acc[j][e]; i1 = e; }
                float ex = expf(v1 - v0);
                float inv = 1.f / (1.f + ex);
                g_top_idx[2*t]   = i0; g_top_scale[2*t]   = inv;
                g_top_idx[2*t+1] = i1; g_top_scale[2*t+1] = ex * inv;
                atomicAdd(&g_counts[i0], 1);
                atomicAdd(&g_counts[i1], 1);
            }
        }
    }
}

// scan (padded to 128) + slot init + scatter: single block
__global__ void __launch_bounds__(1024)
scan_scatter_kernel() {
    if (threadIdx.x == 0) {
        int o = 0;
        for (int e = 0; e < NE; e++) {
            g_offs[e] = o; g_cursor[e] = o; g_ends[e] = o + g_counts[e];
            o += (g_counts[e] + 127) & ~127;
        }
    }
    __syncthreads();
    for (int i = threadIdx.x; i < NSLOTP; i += 1024) g_slot_tok[i] = -1;
    __syncthreads();
    for (int i = threadIdx.x; i < NSLOT; i += 1024) {
        int e = g_top_idx[i];
        int pos = atomicAdd(&g_cursor[e], 1);
        g_slot_tok[pos] = i >> 1;
        g_tok_pos[i] = pos;
    }
}

// gather x rows into slot-tiled layout (zeros for padding slots)
__global__ void __launch_bounds__(256)
xgather_kernel() {
    int u = blockIdx.x * 256 + threadIdx.x;   // one 16B unit
    int seg = u & 7;
    int c = (u >> 3) & 31;
    int slot = u >> 8;
    int tok = g_slot_tok[slot];
    uint4 v = make_uint4(0, 0, 0, 0);
    if (tok >= 0) v = *(const uint4*)(g_x16 + (size_t)tok * HD + c * 64 + seg * 8);
    char* dst = (char*)g_xg + ((size_t)(slot >> 7) * 32 + c) * GU_ABLK
              + (size_t)(slot & 127) * 144 + (size_t)seg * 16;
    *(uint4*)dst = v;
}

// combine: out[t] = s0*down[pos0] + s1*down[pos1]
__global__ void combine_kernel(float* __restrict__ out) {
    int i = blockIdx.x * blockDim.x + threadIdx.x;
    int t  = i >> 9;
    int h4 = i & 511;
    float s0 = g_top_scale[2*t], s1 = g_top_scale[2*t+1];
    int p0 = g_tok_pos[2*t], p1 = g_tok_pos[2*t+1];
    float4 a = ((const float4*)(g_gbuf + (size_t)p0 * HD))[h4];
    float4 b = ((const float4*)(g_gbuf + (size_t)p1 * HD))[h4];
    float4 o;
    o.x = s0*a.x + s1*b.x; o.y = s0*a.y + s1*b.y;
    o.z = s0*a.z + s1*b.z; o.w = s0*a.w + s1*b.w;
    ((float4*)(out + (size_t)t * HD))[h4] = o;
}

// ---------------- gate+up GEMM: bulk-copy pipeline, swiglu epilogue ----------------
__global__ void __launch_bounds__(512, 1)
gemm_gateup() {
    extern __shared__ __align__(128) char sm[];
    __shared__ __align__(8) uint64_t bars[NSTG];
    const int e = blockIdx.z;
    const int row0 = g_offs[e] + blockIdx.y * BM;
    const int rowEnd = g_ends[e];
    if (row0 >= rowEnd) return;
    const int mtile = row0 >> 7;
    const int nt = blockIdx.x;
    const int n0 = nt * 128;

    const char* aBase = (const char*)g_xg + (size_t)mtile * 32 * GU_ABLK;
    const char* b1Base = (const char*)g_w1t + (size_t)(e*16 + nt) * 32 * GU_BBLK;
    const char* b3Base = (const char*)g_w3t + (size_t)(e*16 + nt) * 32 * GU_BBLK;

    const int tid = threadIdx.x;
    const uint32_t sb = smem_u32(sm);
    const uint32_t bb = smem_u32(bars);

    if (tid == 0) {
#pragma unroll
        for (int s = 0; s < NSTG; s++) mbar_init(bb + 8*s, 1);
    }
    __syncthreads();
    if (tid == 0) {
#pragma unroll
        for (int p = 0; p < 2; p++) {
            uint32_t st = sb + p * GU_STG, mb = bb + 8*p;
            mbar_expect(mb, GU_STG);
            bulk_g2s(st,              aBase  + (size_t)p * GU_ABLK, GU_ABLK, mb);
            bulk_g2s(st + GU_ABLK,    b1Base + (size_t)p * GU_BBLK, GU_BBLK, mb);
            bulk_g2s(st + GU_ABLK + GU_BBLK, b3Base + (size_t)p * GU_BBLK, GU_BBLK, mb);
        }
    }

    const int wid = tid >> 5, lane = tid & 31;
    const int wm = wid & 3, wn = wid >> 2;
    const int ar = lane & 15, ac = (lane >> 4) * 8;
    const int br = lane & 15, bc = (lane >> 4) * 8;

    float accG[2][4][4], accU[2][4][4];
#pragma unroll
    for (int mt = 0; mt < 2; mt++)
#pragma unroll
        for (int q4 = 0; q4 < 4; q4++)
#pragma unroll
            for (int q = 0; q < 4; q++) { accG[mt][q4][q] = 0.f; accU[mt][q4][q] = 0.f; }

    for (int c = 0; c < NCHUNK; c++) {
        int s = c % NSTG;
        mbar_wait(bb + 8*s, (c / NSTG) & 1);
        __syncthreads();
        if (tid == 0 && c + 2 < NCHUNK) {
            int s2 = (c + 2) % NSTG;
            uint32_t st = sb + s2 * GU_STG, mb = bb + 8*s2;
            mbar_expect(mb, GU_STG);
            bulk_g2s(st,                     aBase  + (size_t)(c+2) * GU_ABLK, GU_ABLK, mb);
            bulk_g2s(st + GU_ABLK,           b1Base + (size_t)(c+2) * GU_BBLK, GU_BBLK, mb);
            bulk_g2s(st + GU_ABLK + GU_BBLK, b3Base + (size_t)(c+2) * GU_BBLK, GU_BBLK, mb);
        }
        uint32_t stb = sb + (uint32_t)s * GU_STG;

#pragma unroll
        for (int kk = 0; kk < 4; kk++) {
            uint32_t a[2][4];
#pragma unroll
            for (int mt = 0; mt < 2; mt++) {
                uint32_t aaddr = stb
                    + (uint32_t)((wm * 32 + mt * 16 + ar) * 144 + (kk * 16 + ac) * 2);
                ldsm_x4(a[mt], aaddr);
            }
            uint32_t brow = (uint32_t)((kk * 16 + br) * 272);
#pragma unroll
            for (int p = 0; p < 2; p++) {
                uint32_t coff = (uint32_t)((wn * 32 + p * 16 + bc) * 2);
                uint32_t b1[4], b3[4];
                ldsm_x4_t(b1, stb + GU_ABLK + brow + coff);
                ldsm_x4_t(b3, stb + GU_ABLK + GU_BBLK + brow + coff);
                mma16816(accG[0][2*p],   a[0], b1[0], b1[1]);
                mma16816(accG[0][2*p+1], a[0], b1[2], b1[3]);
                mma16816(accG[1][2*p],   a[1], b1[0], b1[1]);
                mma16816(accG[1][2*p+1], a[1], b1[2], b1[3]);
                mma16816(accU[0][2*p],   a[0], b3[0], b3[1]);
                mma16816(accU[0][2*p+1], a[0], b3[2], b3[3]);
                mma16816(accU[1][2*p],   a[1], b3[0], b3[1]);
                mma16816(accU[1][2*p+1], a[1], b3[2], b3[3]);
            }
        }
    }

    // epilogue: act = silu(g)*u -> fp16, written in slot-tiled (DN A) layout
    const int rIn = lane >> 2, cIn = (lane & 3) * 2;
#pragma unroll
    for (int mt = 0; mt < 2; mt++) {
#pragma unroll
        for (int half = 0; half < 2; half++) {
            int slot = row0 + wm * 32 + mt * 16 + rIn + half * 8;
            if (slot < rowEnd) {
                int srow = slot & 127, smt = slot >> 7;
#pragma unroll
                for (int q4 = 0; q4 < 4; q4++) {
                    int col = n0 + wn * 32 + q4 * 8 + cIn;
                    int cch = col >> 6, kl = col & 63;
                    __half* dst = g_actt + ((size_t)smt * 32 + cch) * (DN_ABLK/2)
                                + (size_t)srow * 72 + kl;
                    float a0 = silu_mul(accG[mt][q4][half*2],   accU[mt][q4][half*2]);
                    float a1 = silu_mul(accG[mt][q4][half*2+1], accU[mt][q4][half*2+1]);
                    *(__half2*)dst = __floats2half2_rn(a0, a1);
                }
            }
        }
    }
}

// ---------------- down GEMM: bulk-copy pipeline ----------------
__global__ void __launch_bounds__(512, 1)
gemm_down() {
    extern __shared__ __align__(128) char sm[];
    __shared__ __align__(8) uint64_t bars[NSTG];
    const int e = blockIdx.z;
    const int row0 = g_offs[e] + blockIdx.y * BM;
    const int rowEnd = g_ends[e];
    if (row0 >= rowEnd) return;
    const int mtile = row0 >> 7;
    const int nt = blockIdx.x;
    const int n0 = nt * 256;

    const char* aBase = (const char*)g_actt + (size_t)mtile * 32 * DN_ABLK;
    const char* bBase = (const char*)g_w2t + (size_t)(e*8 + nt) * 32 * DN_BBLK;

    const int tid = threadIdx.x;
    const uint32_t sb = smem_u32(sm);
    const uint32_t bb = smem_u32(bars);

    if (tid == 0) {
#pragma unroll
        for (int s = 0; s < NSTG; s++) mbar_init(bb + 8*s, 1);
    }
    __syncthreads();
    if (tid == 0) {
#pragma unroll
        for (int p = 0; p < 2; p++) {
            uint32_t st = sb + p * DN_STG, mb = bb + 8*p;
            mbar_expect(mb, DN_STG);
            bulk_g2s(st,           aBase + (size_t)p * DN_ABLK, DN_ABLK, mb);
            bulk_g2s(st + DN_ABLK, bBase + (size_t)p * DN_BBLK, DN_BBLK, mb);
        }
    }

    const int wid = tid >> 5, lane = tid & 31;
    const int wm = wid & 3, wn = wid >> 2;
    const int ar = lane & 15, ac = (lane >> 4) * 8;
    const int br = lane & 15, bc = (lane >> 4) * 8;

    float acc[2][8][4];
#pragma unroll
    for (int mt = 0; mt < 2; mt++)
#pragma unroll
        for (int q8 = 0; q8 < 8; q8++)
#pragma unroll
            for (int q = 0; q < 4; q++) acc[mt][q8][q] = 0.f;

    for (int c = 0; c < NCHUNK; c++) {
        int s = c % NSTG;
        mbar_wait(bb + 8*s, (c / NSTG) & 1);
        __syncthreads();
        if (tid == 0 && c + 2 < NCHUNK) {
            int s2 = (c + 2) % NSTG;
            uint32_t st = sb + s2 * DN_STG, mb = bb + 8*s2;
            mbar_expect(mb, DN_STG);
            bulk_g2s(st,           aBase + (size_t)(c+2) * DN_ABLK, DN_ABLK, mb);
            bulk_g2s(st + DN_ABLK, bBase + (size_t)(c+2) * DN_BBLK, DN_BBLK, mb);
        }
        uint32_t stb = sb + (uint32_t)s * DN_STG;

#pragma unroll
        for (int kk = 0; kk < 4; kk++) {
            uint32_t a[2][4];
#pragma unroll
            for (int mt = 0; mt < 2; mt++) {
                uint32_t aaddr = stb
                    + (uint32_t)((wm * 32 + mt * 16 + ar) * 144 + (kk * 16 + ac) * 2);
                ldsm_x4(a[mt], aaddr);
            }
#pragma unroll
            for (int p = 0; p < 4; p++) {
                uint32_t b[4];
                uint32_t baddr = stb + DN_ABLK
                    + (uint32_t)((kk * 16 + br) * 528 + (wn * 64 + p * 16 + bc) * 2);
                ldsm_x4_t(b, baddr);
                mma16816(acc[0][2*p],   a[0], b[0], b[1]);
                mma16816(acc[0][2*p+1], a[0], b[2], b[3]);
                mma16816(acc[1][2*p],   a[1], b[0], b[1]);
                mma16816(acc[1][2*p+1], a[1], b[2], b[3]);
            }
        }
    }

    const int rIn = lane >> 2, cIn = (lane & 3) * 2;
#pragma unroll
    for (int mt = 0; mt < 2; mt++) {
#pragma unroll
        for (int half = 0; half < 2; half++) {
            int slot = row0 + wm * 32 + mt * 16 + rIn + half * 8;
            if (slot < rowEnd) {
                float* Cp = g_gbuf + (size_t)slot * HD + n0 + wn * 64 + cIn;
#pragma unroll
                for (int q8 = 0; q8 < 8; q8++) {
                    float2 v = make_float2(acc[mt][q8][half*2], acc[mt][q8][half*2+1]);
                    *(float2*)(Cp + q8 * 8) = v;
                }
            }
        }
    }
}

// ---------------- host launcher ----------------
extern "C" void kernel_launch(void* const* d_in, const int* in_sizes, int n_in,
                              void* d_out, int out_size) {
    const float* x  = (const float*)d_in[0];
    const float* rw = (const float*)d_in[1];
    const float* w1 = (const float*)d_in[2];
    const float* w3 = (const float*)d_in[3];
    const float* w2 = (const float*)d_in[4];
    float* out = (float*)d_out;

    cudaFuncSetAttribute(gemm_gateup, cudaFuncAttributeMaxDynamicSharedMemorySize, GU_SMEM);
    cudaFuncSetAttribute(gemm_down,   cudaFuncAttributeMaxDynamicSharedMemorySize, DN_SMEM);

    init_small_kernel<<<1, 32>>>();
    prep_kernel<<<NB_PREP, 256>>>(x, rw, w1, w3, w2);
    scan_scatter_kernel<<<1, 1024>>>();
    xgather_kernel<<<NSLOTP, 256>>>();

    dim3 ggu(HD/128, MTMAX, NE);
    gemm_gateup<<<ggu, 512, GU_SMEM>>>();

    dim3 gd(HD/256, MTMAX, NE);
    gemm_down<<<gd, 512, DN_SMEM>>>();

    combine_kernel<<<(TTOK * HD / 4) / 256, 256>>>(out);
}

// round 10
// speedup vs baseline: 3.1119x; 1.0143x over previous
#include <cuda_runtime.h>
#include <cuda_fp16.h>
#include <cstdint>
#include <cstddef>

// Problem constants: T=4096, H=I=2048, E=8, top-2
#define TTOK 4096
#define HD   2048
#define NE   8
#define NSLOT (2*TTOK)
#define NSLOTP 9216
#define MTMAX (NSLOTP/128)     // 72

#define BM 128
#define BKC 64
#define NCHUNK (HD/BKC)        // 32
#define NSTG 3

// gate+up: 128M x 128N dual-B
#define GU_ABLK 18432          // 128 rows x 144B
#define GU_BBLK 17408          // 64 rows x 272B
#define GU_STG  (GU_ABLK + 2*GU_BBLK)   // 53248
#define GU_SMEM (NSTG*GU_STG)           // 159744
// down: 128M x 256N
#define DN_ABLK 18432
#define DN_BBLK 33792          // 64 rows x 528B
#define DN_STG  (DN_ABLK + DN_BBLK)     // 52224

// prep partition
#define NBW 6144
#define NBX 512
#define NBR 128
#define NB_PREP (NBW + NBX + NBR)

#define NPERS 148              // persistent CTAs (1 per SM, <= 148)

// ---------------- device scratch ----------------
__device__ int   g_counts[NE];
__device__ int   g_offs[NE];
__device__ int   g_ends[NE];
__device__ int   g_cursor[NE];
__device__ int   g_top_idx[NSLOT];
__device__ float g_top_scale[NSLOT];
__device__ int   g_slot_tok[NSLOTP];
__device__ int   g_tok_pos[NSLOT];

// persistent-queue state
__device__ int   g_work;
__device__ int   g_nmt;
__device__ int   g_mt_e[MTMAX];
__device__ int   g_xg_done[MTMAX];
__device__ int   g_gu_done[MTMAX];
__device__ int   g_dn_done;

__device__ __align__(16) __half g_x16[(size_t)TTOK*HD];
__device__ __align__(16) __half g_w1t[(size_t)NE*16*32*(GU_BBLK/2)];
__device__ __align__(16) __half g_w3t[(size_t)NE*16*32*(GU_BBLK/2)];
__device__ __align__(16) __half g_w2t[(size_t)NE*8*32*(DN_BBLK/2)];
__device__ __align__(16) __half g_xg[(size_t)MTMAX*32*(GU_ABLK/2)];
__device__ __align__(16) __half g_actt[(size_t)MTMAX*32*(DN_ABLK/2)];
__device__ __align__(16) float  g_gbuf[(size_t)NSLOTP*HD];

// ---------------- helpers ----------------
__device__ __forceinline__ uint32_t smem_u32(const void* p) {
    return (uint32_t)__cvta_generic_to_shared(p);
}
__device__ __forceinline__ void mbar_init(uint32_t a, uint32_t cnt) {
    asm volatile("mbarrier.init.shared.b64 [%0], %1;" :: "r"(a), "r"(cnt) : "memory");
}
__device__ __forceinline__ void mbar_expect(uint32_t a, uint32_t bytes) {
    asm volatile("mbarrier.arrive.expect_tx.shared.b64 _, [%0], %1;"
                 :: "r"(a), "r"(bytes) : "memory");
}
__device__ __forceinline__ void mbar_wait(uint32_t a, uint32_t parity) {
    asm volatile(
        "{\n\t.reg .pred P;\n\t"
        "WL_%=:\n\t"
        "mbarrier.try_wait.parity.shared::cta.b64 P, [%0], %1;\n\t"
        "@P bra WD_%=;\n\t"
        "bra WL_%=;\n\t"
        "WD_%=:\n\t}"
        :: "r"(a), "r"(parity) : "memory");
}
__device__ __forceinline__ void bulk_g2s(uint32_t dst, const void* src,
                                         uint32_t bytes, uint32_t mbar) {
    asm volatile(
        "cp.async.bulk.shared::cta.global.mbarrier::complete_tx::bytes [%0], [%1], %2, [%3];"
        :: "r"(dst), "l"(src), "r"(bytes), "r"(mbar) : "memory");
}
__device__ __forceinline__ void ldsm_x4(uint32_t (&r)[4], uint32_t addr) {
    asm volatile("ldmatrix.sync.aligned.m8n8.x4.shared.b16 {%0,%1,%2,%3}, [%4];\n"
                 : "=r"(r[0]), "=r"(r[1]), "=r"(r[2]), "=r"(r[3]) : "r"(addr));
}
__device__ __forceinline__ void ldsm_x4_t(uint32_t (&r)[4], uint32_t addr) {
    asm volatile("ldmatrix.sync.aligned.m8n8.x4.trans.shared.b16 {%0,%1,%2,%3}, [%4];\n"
                 : "=r"(r[0]), "=r"(r[1]), "=r"(r[2]), "=r"(r[3]) : "r"(addr));
}
__device__ __forceinline__ void mma16816(float (&c)[4], const uint32_t (&a)[4],
                                         uint32_t b0, uint32_t b1) {
    asm volatile(
        "mma.sync.aligned.m16n8k16.row.col.f32.f16.f16.f32 "
        "{%0,%1,%2,%3}, {%4,%5,%6,%7}, {%8,%9}, {%0,%1,%2,%3};\n"
        : "+f"(c[0]), "+f"(c[1]), "+f"(c[2]), "+f"(c[3])
        : "r"(a[0]), "r"(a[1]), "r"(a[2]), "r"(a[3]), "r"(b0), "r"(b1));
}
__device__ __forceinline__ float silu_mul(float g, float u) {
    return u * (g / (1.f + __expf(-g)));
}
__device__ __forceinline__ uint32_t h2u(__half2 h) { return *(uint32_t*)&h; }
__device__ __forceinline__ int ldvol(const int* p) {
    int v;
    asm volatile("ld.volatile.global.b32 %0, [%1];" : "=r"(v) : "l"(p));
    return v;
}

// ---------------- setup ----------------
__global__ void init_small_kernel() {
    int i = threadIdx.x;
    if (i < NE) { g_counts[i] = 0; g_cursor[i] = 0; }
}

// Fused prep: tiled weight converts + x convert + router
__global__ void __launch_bounds__(256)
prep_kernel(const float* __restrict__ x,  const float* __restrict__ rw,
            const float* __restrict__ w1, const float* __restrict__ w3,
            const float* __restrict__ w2) {
    const int bx = blockIdx.x;
    const int tid = threadIdx.x;

    if (bx < NBW) {
        const int which = bx >> 11;
        const int lb = bx & 2047;
        const float* src = (which == 0) ? w1 : (which == 1) ? w3 : w2;
        const size_t U = (size_t)NE * HD * HD / 8;
        const size_t stride = (size_t)2048 * 256;
        for (size_t u = (size_t)lb * 256 + tid; u < U; u += stride) {
            int n8 = (int)(u & 255);
            size_t ek = u >> 8;
            int k = (int)(ek & 2047);
            int e = (int)(ek >> 11);
            const float4* s = (const float4*)src + ek * 512 + n8 * 2;
            float4 v0 = s[0], v1 = s[1];
            uint4 pkt;
            pkt.x = h2u(__floats2half2_rn(v0.x, v0.y));
            pkt.y = h2u(__floats2half2_rn(v0.z, v0.w));
            pkt.z = h2u(__floats2half2_rn(v1.x, v1.y));
            pkt.w = h2u(__floats2half2_rn(v1.z, v1.w));
            char* dst;
            if (which < 2) {
                int nt = n8 >> 4, nl = n8 & 15;
                char* base = (char*)((which == 0) ? g_w1t : g_w3t);
                dst = base + ((size_t)((e*16 + nt)*32 + (k >> 6)))*GU_BBLK
                      + (size_t)(k & 63)*272 + (size_t)nl*16;
            } else {
                int nt = n8 >> 5, nl = n8 & 31;
                dst = (char*)g_w2t + ((size_t)((e*8 + nt)*32 + (k >> 6)))*DN_BBLK
                      + (size_t)(k & 63)*528 + (size_t)nl*16;
            }
            *(uint4*)dst = pkt;
        }
    } else if (bx < NBW + NBX) {
        const int lb = bx - NBW;
        const size_t n4 = ((size_t)TTOK * HD) >> 2;
        const float4* s4 = (const float4*)x;
        __half2* d2 = (__half2*)g_x16;
        const size_t stride = (size_t)NBX * 256;
        for (size_t i = (size_t)lb * 256 + tid; i < n4; i += stride) {
            float4 v = s4[i];
            d2[2*i]   = __floats2half2_rn(v.x, v.y);
            d2[2*i+1] = __floats2half2_rn(v.z, v.w);
        }
    } else {
        const int bi = bx - (NBW + NBX);
        const int warp = tid >> 5, lane = tid & 31;
        const int t0 = (bi * 8 + warp) * 4;
        float acc[4][NE];
#pragma unroll
        for (int j = 0; j < 4; j++)
#pragma unroll
            for (int e = 0; e < NE; e++) acc[j][e] = 0.f;

        const float* xr = x + (size_t)t0 * HD;
        for (int h = lane; h < HD; h += 32) {
            float4 r0 = *(const float4*)(rw + (size_t)h * NE);
            float4 r1 = *(const float4*)(rw + (size_t)h * NE + 4);
            float rv[NE] = {r0.x, r0.y, r0.z, r0.w, r1.x, r1.y, r1.z, r1.w};
#pragma unroll
            for (int j = 0; j < 4; j++) {
                float xv = xr[(size_t)j * HD + h];
#pragma unroll
                for (int e = 0; e < NE; e++) acc[j][e] = fmaf(xv, rv[e], acc[j][e]);
            }
        }
#pragma unroll
        for (int j = 0; j < 4; j++)
#pragma unroll
            for (int e = 0; e < NE; e++) {
#pragma unroll
                for (int o = 16; o; o >>= 1)
                    acc[j][e] += __shfl_xor_sync(0xffffffffu, acc[j][e], o);
            }
        if (lane == 0) {
#pragma unroll
            for (int j = 0; j < 4; j++) {
                int t = t0 + j;
                int i0 = 0; float v0 = acc[j][0];
#pragma unroll
                for (int e = 1; e < NE; e++) if (acc[j][e] > v0) { v0 = acc[j][e]; i0 = e; }
                int i1 = -1; float v1 = -3.4e38f;
#pragma unroll
                for (int e = 0; e < NE; e++)
                    if (e != i0 && acc[j][e] > v1) { v1 = acc[j][e]; i1 = e; }
                float ex = expf(v1 - v0);
                float inv = 1.f / (1.f + ex);
                g_top_idx[2*t]   = i0; g_top_scale[2*t]   = inv;
                g_top_idx[2*t+1] = i1; g_top_scale[2*t+1] = ex * inv;
                atomicAdd(&g_counts[i0], 1);
                atomicAdd(&g_counts[i1], 1);
            }
        }
    }
}

// scan + scatter + queue-state init: single block
__global__ void __launch_bounds__(1024)
scan_scatter_kernel() {
    if (threadIdx.x == 0) {
        int o = 0;
        for (int e = 0; e < NE; e++) {
            g_offs[e] = o; g_cursor[e] = o; g_ends[e] = o + g_counts[e];
            int padded = (g_counts[e] + 127) & ~127;
            for (int m = o >> 7; m < (o + padded) >> 7; m++) g_mt_e[m] = e;
            o += padded;
        }
        g_nmt = o >> 7;
        g_work = 0;
        g_dn_done = 0;
    }
    if (threadIdx.x < MTMAX) { g_xg_done[threadIdx.x] = 0; g_gu_done[threadIdx.x] = 0; }
    __syncthreads();
    for (int i = threadIdx.x; i < NSLOTP; i += 1024) g_slot_tok[i] = -1;
    __syncthreads();
    for (int i = threadIdx.x; i < NSLOT; i += 1024) {
        int e = g_top_idx[i];
        int pos = atomicAdd(&g_cursor[e], 1);
        g_slot_tok[pos] = i >> 1;
        g_tok_pos[i] = pos;
    }
}

// ---------------- work-item bodies ----------------
__device__ void xg_tile(int m, int tid) {
#pragma unroll 4
    for (int i = 0; i < 64; i++) {
        int u = i * 512 + tid;
        int seg = u & 7, c = (u >> 3) & 31, row = u >> 8;
        int tok = g_slot_tok[m * 128 + row];
        uint4 v = make_uint4(0, 0, 0, 0);
        if (tok >= 0) v = *(const uint4*)(g_x16 + (size_t)tok * HD + c * 64 + seg * 8);
        char* dst = (char*)g_xg + ((size_t)m * 32 + c) * GU_ABLK
                  + (size_t)row * 144 + (size_t)seg * 16;
        *(uint4*)dst = v;
    }
}

__device__ void gu_tile(char* sm, uint64_t* bars, int m, int nt, int tid) {
    const int e = g_mt_e[m];
    const int row0 = m * 128;
    const int rowEnd = g_ends[e];
    const int n0 = nt * 128;

    const char* aBase  = (const char*)g_xg  + (size_t)m * 32 * GU_ABLK;
    const char* b1Base = (const char*)g_w1t + (size_t)(e*16 + nt) * 32 * GU_BBLK;
    const char* b3Base = (const char*)g_w3t + (size_t)(e*16 + nt) * 32 * GU_BBLK;

    const uint32_t sb = smem_u32(sm);
    const uint32_t bb = smem_u32(bars);

    if (tid == 0) {
#pragma unroll
        for (int s = 0; s < NSTG; s++) mbar_init(bb + 8*s, 1);
        while (ldvol(&g_xg_done[m]) == 0) {}
    }
    __syncthreads();
    __threadfence();
    if (tid == 0) {
#pragma unroll
        for (int p = 0; p < 2; p++) {
            uint32_t st = sb + p * GU_STG, mb = bb + 8*p;
            mbar_expect(mb, GU_STG);
            bulk_g2s(st,                     aBase  + (size_t)p * GU_ABLK, GU_ABLK, mb);
            bulk_g2s(st + GU_ABLK,           b1Base + (size_t)p * GU_BBLK, GU_BBLK, mb);
            bulk_g2s(st + GU_ABLK + GU_BBLK, b3Base + (size_t)p * GU_BBLK, GU_BBLK, mb);
        }
    }

    const int wid = tid >> 5, lane = tid & 31;
    const int wm = wid & 3, wn = wid >> 2;
    const int ar = lane & 15, ac = (lane >> 4) * 8;
    const int br = lane & 15, bc = (lane >> 4) * 8;

    float accG[2][4][4], accU[2][4][4];
#pragma unroll
    for (int mt = 0; mt < 2; mt++)
#pragma unroll
        for (int q4 = 0; q4 < 4; q4++)
#pragma unroll
            for (int q = 0; q < 4; q++) { accG[mt][q4][q] = 0.f; accU[mt][q4][q] = 0.f; }

    for (int c = 0; c < NCHUNK; c++) {
        int s = c % NSTG;
        mbar_wait(bb + 8*s, (c / NSTG) & 1);
        __syncthreads();
        if (tid == 0 && c + 2 < NCHUNK) {
            int s2 = (c + 2) % NSTG;
            uint32_t st = sb + s2 * GU_STG, mb = bb + 8*s2;
            mbar_expect(mb, GU_STG);
            bulk_g2s(st,                     aBase  + (size_t)(c+2) * GU_ABLK, GU_ABLK, mb);
            bulk_g2s(st + GU_ABLK,           b1Base + (size_t)(c+2) * GU_BBLK, GU_BBLK, mb);
            bulk_g2s(st + GU_ABLK + GU_BBLK, b3Base + (size_t)(c+2) * GU_BBLK, GU_BBLK, mb);
        }
        uint32_t stb = sb + (uint32_t)s * GU_STG;

#pragma unroll
        for (int kk = 0; kk < 4; kk++) {
            uint32_t a[2][4];
#pragma unroll
            for (int mt = 0; mt < 2; mt++) {
                uint32_t aaddr = stb
                    + (uint32_t)((wm * 32 + mt * 16 + ar) * 144 + (kk * 16 + ac) * 2);
                ldsm_x4(a[mt], aaddr);
            }
            uint32_t brow = (uint32_t)((kk * 16 + br) * 272);
#pragma unroll
            for (int p = 0; p < 2; p++) {
                uint32_t coff = (uint32_t)((wn * 32 + p * 16 + bc) * 2);
                uint32_t b1[4], b3[4];
                ldsm_x4_t(b1, stb + GU_ABLK + brow + coff);
                ldsm_x4_t(b3, stb + GU_ABLK + GU_BBLK + brow + coff);
                mma16816(accG[0][2*p],   a[0], b1[0], b1[1]);
                mma16816(accG[0][2*p+1], a[0], b1[2], b1[3]);
                mma16816(accG[1][2*p],   a[1], b1[0], b1[1]);
                mma16816(accG[1][2*p+1], a[1], b1[2], b1[3]);
                mma16816(accU[0][2*p],   a[0], b3[0], b3[1]);
                mma16816(accU[0][2*p+1], a[0], b3[2], b3[3]);
                mma16816(accU[1][2*p],   a[1], b3[0], b3[1]);
                mma16816(accU[1][2*p+1], a[1], b3[2], b3[3]);
            }
        }
    }

    const int rIn = lane >> 2, cIn = (lane & 3) * 2;
#pragma unroll
    for (int mt = 0; mt < 2; mt++) {
#pragma unroll
        for (int half = 0; half < 2; half++) {
            int slot = row0 + wm * 32 + mt * 16 + rIn + half * 8;
            if (slot < rowEnd) {
                int srow = slot & 127, smt = slot >> 7;
#pragma unroll
                for (int q4 = 0; q4 < 4; q4++) {
                    int col = n0 + wn * 32 + q4 * 8 + cIn;
                    int cch = col >> 6, kl = col & 63;
                    __half* dst = g_actt + ((size_t)smt * 32 + cch) * (DN_ABLK/2)
                                + (size_t)srow * 72 + kl;
                    float a0 = silu_mul(accG[mt][q4][half*2],   accU[mt][q4][half*2]);
                    float a1 = silu_mul(accG[mt][q4][half*2+1], accU[mt][q4][half*2+1]);
                    *(__half2*)dst = __floats2half2_rn(a0, a1);
                }
            }
        }
    }
    __threadfence();
    __syncthreads();
    if (tid == 0) atomicAdd(&g_gu_done[m], 1);
}

__device__ void dn_tile(char* sm, uint64_t* bars, int m, int nt, int tid) {
    const int e = g_mt_e[m];
    const int row0 = m * 128;
    const int rowEnd = g_ends[e];
    const int n0 = nt * 256;

    const char* aBase = (const char*)g_actt + (size_t)m * 32 * DN_ABLK;
    const char* bBase = (const char*)g_w2t + (size_t)(e*8 + nt) * 32 * DN_BBLK;

    const uint32_t sb = smem_u32(sm);
    const uint32_t bb = smem_u32(bars);

    if (tid == 0) {
#pragma unroll
        for (int s = 0; s < NSTG; s++) mbar_init(bb + 8*s, 1);
        while (ldvol(&g_gu_done[m]) < 16) {}
    }
    __syncthreads();
    __threadfence();
    if (tid == 0) {
#pragma unroll
        for (int p = 0; p < 2; p++) {
            uint32_t st = sb + p * DN_STG, mb = bb + 8*p;
            mbar_expect(mb, DN_STG);
            bulk_g2s(st,           aBase + (size_t)p * DN_ABLK, DN_ABLK, mb);
            bulk_g2s(st + DN_ABLK, bBase + (size_t)p * DN_BBLK, DN_BBLK, mb);
        }
    }

    const int wid = tid >> 5, lane = tid & 31;
    const int wm = wid & 3, wn = wid >> 2;
    const int ar = lane & 15, ac = (lane >> 4) * 8;
    const int br = lane & 15, bc = (lane >> 4) * 8;

    float acc[2][8][4];
#pragma unroll
    for (int mt = 0; mt < 2; mt++)
#pragma unroll
        for (int q8 = 0; q8 < 8; q8++)
#pragma unroll
            for (int q = 0; q < 4; q++) acc[mt][q8][q] = 0.f;

    for (int c = 0; c < NCHUNK; c++) {
        int s = c % NSTG;
        mbar_wait(bb + 8*s, (c / NSTG) & 1);
        __syncthreads();
        if (tid == 0 && c + 2 < NCHUNK) {
            int s2 = (c + 2) % NSTG;
            uint32_t st = sb + s2 * DN_STG, mb = bb + 8*s2;
            mbar_expect(mb, DN_STG);
            bulk_g2s(st,           aBase + (size_t)(c+2) * DN_ABLK, DN_ABLK, mb);
            bulk_g2s(st + DN_ABLK, bBase + (size_t)(c+2) * DN_BBLK, DN_BBLK, mb);
        }
        uint32_t stb = sb + (uint32_t)s * DN_STG;

#pragma unroll
        for (int kk = 0; kk < 4; kk++) {
            uint32_t a[2][4];
#pragma unroll
            for (int mt = 0; mt < 2; mt++) {
                uint32_t aaddr = stb
                    + (uint32_t)((wm * 32 + mt * 16 + ar) * 144 + (kk * 16 + ac) * 2);
                ldsm_x4(a[mt], aaddr);
            }
#pragma unroll
            for (int p = 0; p < 4; p++) {
                uint32_t b[4];
                uint32_t baddr = stb + DN_ABLK
                    + (uint32_t)((kk * 16 + br) * 528 + (wn * 64 + p * 16 + bc) * 2);
                ldsm_x4_t(b, baddr);
                mma16816(acc[0][2*p],   a[0], b[0], b[1]);
                mma16816(acc[0][2*p+1], a[0], b[2], b[3]);
                mma16816(acc[1][2*p],   a[1], b[0], b[1]);
                mma16816(acc[1][2*p+1], a[1], b[2], b[3]);
            }
        }
    }

    const int rIn = lane >> 2, cIn = (lane & 3) * 2;
#pragma unroll
    for (int mt = 0; mt < 2; mt++) {
#pragma unroll
        for (int half = 0; half < 2; half++) {
            int slot = row0 + wm * 32 + mt * 16 + rIn + half * 8;
            if (slot < rowEnd) {
                float* Cp = g_gbuf + (size_t)slot * HD + n0 + wn * 64 + cIn;
#pragma unroll
                for (int q8 = 0; q8 < 8; q8++) {
                    float2 v = make_float2(acc[mt][q8][half*2], acc[mt][q8][half*2+1]);
                    *(float2*)(Cp + q8 * 8) = v;
                }
            }
        }
    }
    __threadfence();
    __syncthreads();
    if (tid == 0) atomicAdd(&g_dn_done, 1);
}

// ---------------- persistent scheduler kernel ----------------
__global__ void __launch_bounds__(512, 1)
moe_persistent(float* __restrict__ out) {
    extern __shared__ __align__(128) char sm[];
    __shared__ __align__(8) uint64_t bars[NSTG];
    __shared__ int sh_w;
    const int tid = threadIdx.x;
    const int nmt = g_nmt;
    const int nXG = nmt, nGU = nmt * 16, nDN = nmt * 8;
    const int total = nXG + nGU + nDN;

    for (;;) {
        if (tid == 0) sh_w = atomicAdd(&g_work, 1);
        __syncthreads();
        int w = sh_w;
        if (w >= total) break;
        if (w < nXG) {
            xg_tile(w, tid);
            __threadfence();
            __syncthreads();
            if (tid == 0) atomicExch(&g_xg_done[w], 1);
        } else if (w < nXG + nGU) {
            int i = w - nXG;
            gu_tile(sm, bars, i >> 4, i & 15, tid);
        } else {
            int i = w - nXG - nGU;
            dn_tile(sm, bars, i >> 3, i & 7, tid);
        }
        __syncthreads();
    }

    // combine phase: wait for all down tiles, then out[t] = s0*y[p0] + s1*y[p1]
    if (tid == 0) { while (ldvol(&g_dn_done) < nDN) {} }
    __syncthreads();
    __threadfence();
    const int N4 = TTOK * HD / 4;
    for (int i = blockIdx.x * 512 + tid; i < N4; i += NPERS * 512) {
        int t  = i >> 9;
        int h4 = i & 511;
        float s0 = g_top_scale[2*t], s1 = g_top_scale[2*t+1];
        int p0 = g_tok_pos[2*t], p1 = g_tok_pos[2*t+1];
        float4 a = __ldcg((const float4*)(g_gbuf + (size_t)p0 * HD) + h4);
        float4 b = __ldcg((const float4*)(g_gbuf + (size_t)p1 * HD) + h4);
        float4 o;
        o.x = s0*a.x + s1*b.x; o.y = s0*a.y + s1*b.y;
        o.z = s0*a.z + s1*b.z; o.w = s0*a.w + s1*b.w;
        ((float4*)(out + (size_t)t * HD))[h4] = o;
    }
}

// ---------------- host launcher ----------------
extern "C" void kernel_launch(void* const* d_in, const int* in_sizes, int n_in,
                              void* d_out, int out_size) {
    const float* x  = (const float*)d_in[0];
    const float* rw = (const float*)d_in[1];
    const float* w1 = (const float*)d_in[2];
    const float* w3 = (const float*)d_in[3];
    const float* w2 = (const float*)d_in[4];
    float* out = (float*)d_out;

    cudaFuncSetAttribute(moe_persistent, cudaFuncAttributeMaxDynamicSharedMemorySize, GU_SMEM);

    init_small_kernel<<<1, 32>>>();
    prep_kernel<<<NB_PREP, 256>>>(x, rw, w1, w3, w2);
    scan_scatter_kernel<<<1, 1024>>>();
    moe_persistent<<<NPERS, 512, GU_SMEM>>>(out);
}